// round 1
// baseline (speedup 1.0000x reference)
#include <cuda_runtime.h>
#include <cuda_bf16.h>
#include <math.h>

#define S_LEN 2048
#define HID   2048
#define NH    32
#define NKV   8
#define HD    64

// ---------------- static scratch (no runtime allocation allowed) ----------------
static __device__ float g_scale[4];
static __device__ float g_part[4 * 256];
static __device__ float g_wq[HID * HID];
static __device__ float g_wk[NKV * HD * HID];
static __device__ float g_wv[NKV * HD * HID];
static __device__ float g_wo[HID * HID];
static __device__ float g_q[S_LEN * HID];
static __device__ float g_k[S_LEN * NKV * HD];
static __device__ float g_v[S_LEN * NKV * HD];
static __device__ float g_att[S_LEN * HID];

// ---------------- absmean reduction (deterministic two-stage) ----------------
__global__ void absmean_partial(const float* __restrict__ w, int n, float* __restrict__ part) {
    __shared__ float red[256];
    float s = 0.f;
    for (int i = blockIdx.x * blockDim.x + threadIdx.x; i < n; i += gridDim.x * blockDim.x)
        s += fabsf(w[i]);
    red[threadIdx.x] = s;
    __syncthreads();
    for (int o = 128; o > 0; o >>= 1) {
        if (threadIdx.x < o) red[threadIdx.x] += red[threadIdx.x + o];
        __syncthreads();
    }
    if (threadIdx.x == 0) part[blockIdx.x] = red[0];
}

__global__ void absmean_final(const float* __restrict__ part, int n, float* __restrict__ scale) {
    __shared__ float red[256];
    red[threadIdx.x] = part[threadIdx.x];
    __syncthreads();
    for (int o = 128; o > 0; o >>= 1) {
        if (threadIdx.x < o) red[threadIdx.x] += red[threadIdx.x + o];
        __syncthreads();
    }
    if (threadIdx.x == 0) *scale = red[0] / (float)n + 1e-6f;
}

// ---------------- ternary quantization ----------------
__global__ void quantize_w(const float* __restrict__ w, float* __restrict__ out, int n,
                           const float* __restrict__ scale_p) {
    int i = blockIdx.x * blockDim.x + threadIdx.x;
    if (i >= n) return;
    float s = *scale_p;
    float inv = 1.f / s;
    float t = rintf(fminf(fmaxf(w[i] * inv, -1.f), 1.f));
    out[i] = t * s;
}

// ---------------- tiled SGEMM, C[M,N] = A[M,K] * B[N,K]^T (NT) ----------------
// M,N multiples of 64, K multiple of 16.
#define BM 64
#define BN 64
#define BKG 16
__global__ __launch_bounds__(256) void sgemm_nt(const float* __restrict__ A,
                                                const float* __restrict__ B,
                                                float* __restrict__ C,
                                                int M, int N, int K) {
    __shared__ float As[BKG][BM];
    __shared__ float Bs[BKG][BN];
    int tid = threadIdx.x;
    int tx = tid % 16, ty = tid / 16;
    int lrow = tid / 4;           // 0..63
    int lcol = (tid % 4) * 4;     // 0,4,8,12
    const float* Ab = A + (blockIdx.y * BM) * K;
    const float* Bb = B + (blockIdx.x * BN) * K;
    float acc[4][4] = {};
    for (int k0 = 0; k0 < K; k0 += BKG) {
        float4 av = *(const float4*)(Ab + lrow * K + k0 + lcol);
        float4 bv = *(const float4*)(Bb + lrow * K + k0 + lcol);
        As[lcol + 0][lrow] = av.x; As[lcol + 1][lrow] = av.y;
        As[lcol + 2][lrow] = av.z; As[lcol + 3][lrow] = av.w;
        Bs[lcol + 0][lrow] = bv.x; Bs[lcol + 1][lrow] = bv.y;
        Bs[lcol + 2][lrow] = bv.z; Bs[lcol + 3][lrow] = bv.w;
        __syncthreads();
#pragma unroll
        for (int k = 0; k < BKG; k++) {
            float4 a = *(const float4*)&As[k][ty * 4];
            float4 b = *(const float4*)&Bs[k][tx * 4];
            float ar[4] = {a.x, a.y, a.z, a.w};
            float br[4] = {b.x, b.y, b.z, b.w};
#pragma unroll
            for (int i = 0; i < 4; i++)
#pragma unroll
                for (int j = 0; j < 4; j++)
                    acc[i][j] += ar[i] * br[j];
        }
        __syncthreads();
    }
    int crow = blockIdx.y * BM + ty * 4;
    int ccol = blockIdx.x * BN + tx * 4;
#pragma unroll
    for (int i = 0; i < 4; i++) {
        float4 v = make_float4(acc[i][0], acc[i][1], acc[i][2], acc[i][3]);
        *(float4*)(C + (crow + i) * N + ccol) = v;
    }
}

// ---------------- RoPE (in place), x layout [S, nheads, 64] ----------------
__global__ void rope_kernel(float* __restrict__ x, const int* __restrict__ pos_ids, int nheads) {
    int idx = blockIdx.x * blockDim.x + threadIdx.x;
    int total = S_LEN * nheads * 32;
    if (idx >= total) return;
    int i = idx & 31;
    int h = (idx >> 5) % nheads;
    int s = idx / (32 * nheads);
    float pos = (float)pos_ids[s];
    float inv_freq = powf(10000.f, -(float)(2 * i) / 64.f);
    float ang = pos * inv_freq;
    float c = cosf(ang), sn = sinf(ang);
    float* base = x + (s * nheads + h) * HD;
    float x1 = base[i], x2 = base[i + 32];
    base[i]      = x1 * c - x2 * sn;
    base[i + 32] = x2 * c + x1 * sn;
}

// ---------------- flash attention ----------------
// Q: [S, NH*64], K/V: [S, NKV*64], mask: [S] additive over keys, O: [S, NH*64]
#define BQ  128
#define BKV 32
__global__ __launch_bounds__(128) void flash_attn(const float* __restrict__ Q,
                                                  const float* __restrict__ Kg,
                                                  const float* __restrict__ Vg,
                                                  const float* __restrict__ mask,
                                                  float* __restrict__ O) {
    __shared__ float Ks[BKV][HD];
    __shared__ float Vs[BKV][HD];
    int h = blockIdx.y;
    int kvh = h >> 2;  // NH/NKV = 4
    int row = blockIdx.x * BQ + threadIdx.x;

    float q[HD];
    const float* qp = Q + row * HID + h * HD;
#pragma unroll
    for (int j = 0; j < HD; j += 4) {
        float4 v = *(const float4*)(qp + j);
        q[j] = v.x * 0.125f; q[j + 1] = v.y * 0.125f;
        q[j + 2] = v.z * 0.125f; q[j + 3] = v.w * 0.125f;
    }

    float o[HD];
#pragma unroll
    for (int j = 0; j < HD; j++) o[j] = 0.f;
    float m = -1e30f, l = 0.f;

    for (int t = 0; t < S_LEN; t += BKV) {
        // cooperative tile load: BKV*16 float4 per tile
        for (int u = threadIdx.x; u < BKV * 16; u += BQ) {
            int r = u >> 4, c4 = u & 15;
            ((float4*)Ks[r])[c4] = *(const float4*)(Kg + (t + r) * (NKV * HD) + kvh * HD + c4 * 4);
            ((float4*)Vs[r])[c4] = *(const float4*)(Vg + (t + r) * (NKV * HD) + kvh * HD + c4 * 4);
        }
        __syncthreads();

        float s[BKV];
        float tmax = -1e30f;
#pragma unroll
        for (int kk = 0; kk < BKV; kk++) {
            float acc = 0.f;
#pragma unroll
            for (int j = 0; j < HD; j++) acc += q[j] * Ks[kk][j];
            acc += mask[t + kk];
            s[kk] = acc;
            tmax = fmaxf(tmax, acc);
        }
        float mnew = fmaxf(m, tmax);
        float corr = __expf(m - mnew);
        l *= corr;
#pragma unroll
        for (int j = 0; j < HD; j++) o[j] *= corr;
#pragma unroll
        for (int kk = 0; kk < BKV; kk++) {
            float p = __expf(s[kk] - mnew);
            l += p;
#pragma unroll
            for (int j = 0; j < HD; j++) o[j] += p * Vs[kk][j];
        }
        m = mnew;
        __syncthreads();
    }

    float invl = 1.f / l;
    float* op = O + row * HID + h * HD;
#pragma unroll
    for (int j = 0; j < HD; j += 4) {
        float4 v = make_float4(o[j] * invl, o[j + 1] * invl, o[j + 2] * invl, o[j + 3] * invl);
        *(float4*)(op + j) = v;
    }
}

// ---------------- host launcher ----------------
extern "C" void kernel_launch(void* const* d_in, const int* in_sizes, int n_in,
                              void* d_out, int out_size) {
    const float* x    = (const float*)d_in[0];
    const float* mask = (const float*)d_in[1];
    const int*   pos  = (const int*)d_in[2];
    const float* wq   = (const float*)d_in[3];
    const float* wk   = (const float*)d_in[4];
    const float* wv   = (const float*)d_in[5];
    const float* wo   = (const float*)d_in[6];
    float* out = (float*)d_out;

    float *pscale, *ppart, *pwq, *pwk, *pwv, *pwo, *pq, *pk, *pv, *patt;
    cudaGetSymbolAddress((void**)&pscale, g_scale);
    cudaGetSymbolAddress((void**)&ppart,  g_part);
    cudaGetSymbolAddress((void**)&pwq,    g_wq);
    cudaGetSymbolAddress((void**)&pwk,    g_wk);
    cudaGetSymbolAddress((void**)&pwv,    g_wv);
    cudaGetSymbolAddress((void**)&pwo,    g_wo);
    cudaGetSymbolAddress((void**)&pq,     g_q);
    cudaGetSymbolAddress((void**)&pk,     g_k);
    cudaGetSymbolAddress((void**)&pv,     g_v);
    cudaGetSymbolAddress((void**)&patt,   g_att);

    const int n_big = HID * HID;           // 4194304
    const int n_kv  = NKV * HD * HID;      // 1048576

    // scales (deterministic two-stage reduction)
    absmean_partial<<<256, 256>>>(wq, n_big, ppart + 0 * 256);
    absmean_final<<<1, 256>>>(ppart + 0 * 256, n_big, pscale + 0);
    absmean_partial<<<256, 256>>>(wk, n_kv, ppart + 1 * 256);
    absmean_final<<<1, 256>>>(ppart + 1 * 256, n_kv, pscale + 1);
    absmean_partial<<<256, 256>>>(wv, n_kv, ppart + 2 * 256);
    absmean_final<<<1, 256>>>(ppart + 2 * 256, n_kv, pscale + 2);
    absmean_partial<<<256, 256>>>(wo, n_big, ppart + 3 * 256);
    absmean_final<<<1, 256>>>(ppart + 3 * 256, n_big, pscale + 3);

    // quantize
    quantize_w<<<n_big / 256, 256>>>(wq, pwq, n_big, pscale + 0);
    quantize_w<<<n_kv / 256, 256>>>(wk, pwk, n_kv, pscale + 1);
    quantize_w<<<n_kv / 256, 256>>>(wv, pwv, n_kv, pscale + 2);
    quantize_w<<<n_big / 256, 256>>>(wo, pwo, n_big, pscale + 3);

    // projections: C = X @ W^T
    sgemm_nt<<<dim3(HID / BN, S_LEN / BM), 256>>>(x, pwq, pq, S_LEN, HID, HID);
    sgemm_nt<<<dim3((NKV * HD) / BN, S_LEN / BM), 256>>>(x, pwk, pk, S_LEN, NKV * HD, HID);
    sgemm_nt<<<dim3((NKV * HD) / BN, S_LEN / BM), 256>>>(x, pwv, pv, S_LEN, NKV * HD, HID);

    // RoPE
    rope_kernel<<<(S_LEN * NH * 32 + 255) / 256, 256>>>(pq, pos, NH);
    rope_kernel<<<(S_LEN * NKV * 32 + 255) / 256, 256>>>(pk, pos, NKV);

    // attention
    flash_attn<<<dim3(S_LEN / BQ, NH), BQ>>>(pq, pk, pv, mask, patt);

    // output projection -> d_out
    sgemm_nt<<<dim3(HID / BN, S_LEN / BM), 256>>>(patt, pwo, out, S_LEN, HID, HID);
}

// round 2
// speedup vs baseline: 1.5434x; 1.5434x over previous
#include <cuda_runtime.h>
#include <cuda_bf16.h>
#include <math.h>

#define S_LEN 2048
#define HID   2048
#define NH    32
#define NKV   8
#define HD    64

// ---------------- static scratch (no runtime allocation allowed) ----------------
static __device__ float g_scale[4];
static __device__ float g_part[4 * 256];
static __device__ float g_q[S_LEN * HID];
static __device__ float g_k[S_LEN * NKV * HD];
static __device__ float g_v[S_LEN * NKV * HD];
static __device__ float g_att[S_LEN * HID];

// ---------------- absmean reduction (deterministic two-stage) ----------------
__global__ void absmean_partial(const float* __restrict__ w, int n, float* __restrict__ part) {
    __shared__ float red[256];
    float s = 0.f;
    for (int i = blockIdx.x * blockDim.x + threadIdx.x; i < n; i += gridDim.x * blockDim.x)
        s += fabsf(w[i]);
    red[threadIdx.x] = s;
    __syncthreads();
    for (int o = 128; o > 0; o >>= 1) {
        if (threadIdx.x < o) red[threadIdx.x] += red[threadIdx.x + o];
        __syncthreads();
    }
    if (threadIdx.x == 0) part[blockIdx.x] = red[0];
}

__global__ void absmean_final(const float* __restrict__ part, int n, float* __restrict__ scale) {
    __shared__ float red[256];
    red[threadIdx.x] = part[threadIdx.x];
    __syncthreads();
    for (int o = 128; o > 0; o >>= 1) {
        if (threadIdx.x < o) red[threadIdx.x] += red[threadIdx.x + o];
        __syncthreads();
    }
    if (threadIdx.x == 0) *scale = red[0] / (float)n + 1e-6f;
}

// ---------------- tf32 helpers ----------------
__device__ __forceinline__ unsigned f2tf32(float x) {
    unsigned r;
    asm("cvt.rna.tf32.f32 %0, %1;" : "=r"(r) : "f"(x));
    return r;
}

__device__ __forceinline__ void mma_tf32(float c[4], const unsigned a[4], const unsigned b[2]) {
    asm volatile(
        "mma.sync.aligned.m16n8k8.row.col.f32.tf32.tf32.f32 "
        "{%0,%1,%2,%3}, {%4,%5,%6,%7}, {%8,%9}, {%0,%1,%2,%3};"
        : "+f"(c[0]), "+f"(c[1]), "+f"(c[2]), "+f"(c[3])
        : "r"(a[0]), "r"(a[1]), "r"(a[2]), "r"(a[3]), "r"(b[0]), "r"(b[1]));
}

// ---------------- tensor-core GEMM: C[M,N] = A[M,K] * quant(W)[N,K]^T ----------------
// Block tile 128x128x32. 8 warps: 2(M) x 4(N), warp tile 64x32.
// Inline ternary quantization of W during the B-tile load.
#define GBM 128
#define GBN 128
#define GBK 32
#define PAD 36

__global__ __launch_bounds__(256) void mma_gemm(const float* __restrict__ A,
                                                const float* __restrict__ W,
                                                float* __restrict__ C,
                                                int M, int N, int K,
                                                const float* __restrict__ scale_p) {
    __shared__ unsigned As[GBM][PAD];
    __shared__ unsigned Bs[GBN][PAD];

    const int tid = threadIdx.x;
    const float scale = *scale_p;
    const float inv = 1.f / scale;

    const int bm = blockIdx.y * GBM;
    const int bn = blockIdx.x * GBN;

    const int lr = tid >> 3;          // 0..31 (base row within tile)
    const int lc = (tid & 7) * 4;     // 0..28, float4 column

    const int warp = tid >> 5, lane = tid & 31;
    const int wm = (warp & 1) * 64;   // warp M offset
    const int wn = (warp >> 1) * 32;  // warp N offset
    const int g = lane >> 2, tg = lane & 3;

    float c[4][4][4] = {};

    const float* Ap = A + (size_t)bm * K;
    const float* Wp = W + (size_t)bn * K;

    float4 fa[4], fb[4];
#pragma unroll
    for (int i = 0; i < 4; i++) {
        fa[i] = *(const float4*)(Ap + (size_t)(lr + 32 * i) * K + lc);
        fb[i] = *(const float4*)(Wp + (size_t)(lr + 32 * i) * K + lc);
    }

    for (int k0 = 0; k0 < K; k0 += GBK) {
        __syncthreads();  // previous compute done before overwriting smem
#pragma unroll
        for (int i = 0; i < 4; i++) {
            int r = lr + 32 * i;
            As[r][lc + 0] = f2tf32(fa[i].x);
            As[r][lc + 1] = f2tf32(fa[i].y);
            As[r][lc + 2] = f2tf32(fa[i].z);
            As[r][lc + 3] = f2tf32(fa[i].w);
            float qx = rintf(fminf(fmaxf(fb[i].x * inv, -1.f), 1.f)) * scale;
            float qy = rintf(fminf(fmaxf(fb[i].y * inv, -1.f), 1.f)) * scale;
            float qz = rintf(fminf(fmaxf(fb[i].z * inv, -1.f), 1.f)) * scale;
            float qw = rintf(fminf(fmaxf(fb[i].w * inv, -1.f), 1.f)) * scale;
            Bs[r][lc + 0] = f2tf32(qx);
            Bs[r][lc + 1] = f2tf32(qy);
            Bs[r][lc + 2] = f2tf32(qz);
            Bs[r][lc + 3] = f2tf32(qw);
        }
        __syncthreads();

        // prefetch next k tile into registers (overlaps with compute)
        if (k0 + GBK < K) {
#pragma unroll
            for (int i = 0; i < 4; i++) {
                fa[i] = *(const float4*)(Ap + (size_t)(lr + 32 * i) * K + k0 + GBK + lc);
                fb[i] = *(const float4*)(Wp + (size_t)(lr + 32 * i) * K + k0 + GBK + lc);
            }
        }

#pragma unroll
        for (int ks = 0; ks < GBK; ks += 8) {
            unsigned a[4][4], b[4][2];
#pragma unroll
            for (int mt = 0; mt < 4; mt++) {
                int r = wm + mt * 16 + g;
                a[mt][0] = As[r][ks + tg];
                a[mt][1] = As[r + 8][ks + tg];
                a[mt][2] = As[r][ks + tg + 4];
                a[mt][3] = As[r + 8][ks + tg + 4];
            }
#pragma unroll
            for (int nt = 0; nt < 4; nt++) {
                int nr = wn + nt * 8 + g;
                b[nt][0] = Bs[nr][ks + tg];
                b[nt][1] = Bs[nr][ks + tg + 4];
            }
#pragma unroll
            for (int mt = 0; mt < 4; mt++)
#pragma unroll
                for (int nt = 0; nt < 4; nt++)
                    mma_tf32(c[mt][nt], a[mt], b[nt]);
        }
    }

    // epilogue
#pragma unroll
    for (int mt = 0; mt < 4; mt++) {
#pragma unroll
        for (int nt = 0; nt < 4; nt++) {
            int row = bm + wm + mt * 16 + g;
            int col = bn + wn + nt * 8 + 2 * tg;
            *(float2*)(C + (size_t)row * N + col) = make_float2(c[mt][nt][0], c[mt][nt][1]);
            *(float2*)(C + (size_t)(row + 8) * N + col) = make_float2(c[mt][nt][2], c[mt][nt][3]);
        }
    }
}

// ---------------- RoPE (in place), x layout [S, nheads, 64] ----------------
__global__ void rope_kernel(float* __restrict__ x, const int* __restrict__ pos_ids, int nheads) {
    int idx = blockIdx.x * blockDim.x + threadIdx.x;
    int total = S_LEN * nheads * 32;
    if (idx >= total) return;
    int i = idx & 31;
    int h = (idx >> 5) % nheads;
    int s = idx / (32 * nheads);
    float pos = (float)pos_ids[s];
    float inv_freq = powf(10000.f, -(float)(2 * i) / 64.f);
    float ang = pos * inv_freq;
    float c = cosf(ang), sn = sinf(ang);
    float* base = x + (s * nheads + h) * HD;
    float x1 = base[i], x2 = base[i + 32];
    base[i]      = x1 * c - x2 * sn;
    base[i + 32] = x2 * c + x1 * sn;
}

// ---------------- flash attention ----------------
#define BQ  128
#define BKV 32
__global__ __launch_bounds__(128) void flash_attn(const float* __restrict__ Q,
                                                  const float* __restrict__ Kg,
                                                  const float* __restrict__ Vg,
                                                  const float* __restrict__ mask,
                                                  float* __restrict__ O) {
    __shared__ float Ks[BKV][HD];
    __shared__ float Vs[BKV][HD];
    int h = blockIdx.y;
    int kvh = h >> 2;
    int row = blockIdx.x * BQ + threadIdx.x;

    float q[HD];
    const float* qp = Q + row * HID + h * HD;
#pragma unroll
    for (int j = 0; j < HD; j += 4) {
        float4 v = *(const float4*)(qp + j);
        q[j] = v.x * 0.125f; q[j + 1] = v.y * 0.125f;
        q[j + 2] = v.z * 0.125f; q[j + 3] = v.w * 0.125f;
    }

    float o[HD];
#pragma unroll
    for (int j = 0; j < HD; j++) o[j] = 0.f;
    float m = -1e30f, l = 0.f;

    for (int t = 0; t < S_LEN; t += BKV) {
        for (int u = threadIdx.x; u < BKV * 16; u += BQ) {
            int r = u >> 4, c4 = u & 15;
            ((float4*)Ks[r])[c4] = *(const float4*)(Kg + (t + r) * (NKV * HD) + kvh * HD + c4 * 4);
            ((float4*)Vs[r])[c4] = *(const float4*)(Vg + (t + r) * (NKV * HD) + kvh * HD + c4 * 4);
        }
        __syncthreads();

        float s[BKV];
        float tmax = -1e30f;
#pragma unroll
        for (int kk = 0; kk < BKV; kk++) {
            float acc = 0.f;
#pragma unroll
            for (int j = 0; j < HD; j++) acc += q[j] * Ks[kk][j];
            acc += mask[t + kk];
            s[kk] = acc;
            tmax = fmaxf(tmax, acc);
        }
        float mnew = fmaxf(m, tmax);
        float corr = __expf(m - mnew);
        l *= corr;
#pragma unroll
        for (int j = 0; j < HD; j++) o[j] *= corr;
#pragma unroll
        for (int kk = 0; kk < BKV; kk++) {
            float p = __expf(s[kk] - mnew);
            l += p;
#pragma unroll
            for (int j = 0; j < HD; j++) o[j] += p * Vs[kk][j];
        }
        m = mnew;
        __syncthreads();
    }

    float invl = 1.f / l;
    float* op = O + row * HID + h * HD;
#pragma unroll
    for (int j = 0; j < HD; j += 4) {
        float4 v = make_float4(o[j] * invl, o[j + 1] * invl, o[j + 2] * invl, o[j + 3] * invl);
        *(float4*)(op + j) = v;
    }
}

// ---------------- host launcher ----------------
extern "C" void kernel_launch(void* const* d_in, const int* in_sizes, int n_in,
                              void* d_out, int out_size) {
    const float* x    = (const float*)d_in[0];
    const float* mask = (const float*)d_in[1];
    const int*   pos  = (const int*)d_in[2];
    const float* wq   = (const float*)d_in[3];
    const float* wk   = (const float*)d_in[4];
    const float* wv   = (const float*)d_in[5];
    const float* wo   = (const float*)d_in[6];
    float* out = (float*)d_out;

    float *pscale, *ppart, *pq, *pk, *pv, *patt;
    cudaGetSymbolAddress((void**)&pscale, g_scale);
    cudaGetSymbolAddress((void**)&ppart,  g_part);
    cudaGetSymbolAddress((void**)&pq,     g_q);
    cudaGetSymbolAddress((void**)&pk,     g_k);
    cudaGetSymbolAddress((void**)&pv,     g_v);
    cudaGetSymbolAddress((void**)&patt,   g_att);

    const int n_big = HID * HID;
    const int n_kv  = NKV * HD * HID;

    absmean_partial<<<256, 256>>>(wq, n_big, ppart + 0 * 256);
    absmean_final<<<1, 256>>>(ppart + 0 * 256, n_big, pscale + 0);
    absmean_partial<<<256, 256>>>(wk, n_kv, ppart + 1 * 256);
    absmean_final<<<1, 256>>>(ppart + 1 * 256, n_kv, pscale + 1);
    absmean_partial<<<256, 256>>>(wv, n_kv, ppart + 2 * 256);
    absmean_final<<<1, 256>>>(ppart + 2 * 256, n_kv, pscale + 2);
    absmean_partial<<<256, 256>>>(wo, n_big, ppart + 3 * 256);
    absmean_final<<<1, 256>>>(ppart + 3 * 256, n_big, pscale + 3);

    // projections with fused quantization (tensor cores, tf32)
    mma_gemm<<<dim3(HID / GBN, S_LEN / GBM), 256>>>(x, wq, pq, S_LEN, HID, HID, pscale + 0);
    mma_gemm<<<dim3((NKV * HD) / GBN, S_LEN / GBM), 256>>>(x, wk, pk, S_LEN, NKV * HD, HID, pscale + 1);
    mma_gemm<<<dim3((NKV * HD) / GBN, S_LEN / GBM), 256>>>(x, wv, pv, S_LEN, NKV * HD, HID, pscale + 2);

    rope_kernel<<<(S_LEN * NH * 32 + 255) / 256, 256>>>(pq, pos, NH);
    rope_kernel<<<(S_LEN * NKV * 32 + 255) / 256, 256>>>(pk, pos, NKV);

    flash_attn<<<dim3(S_LEN / BQ, NH), BQ>>>(pq, pk, pv, mask, patt);

    mma_gemm<<<dim3(HID / GBN, S_LEN / GBM), 256>>>(patt, wo, out, S_LEN, HID, HID, pscale + 3);
}

// round 3
// speedup vs baseline: 3.3495x; 2.1703x over previous
#include <cuda_runtime.h>
#include <cuda_bf16.h>
#include <math.h>

#define S_LEN 2048
#define HID   2048
#define NH    32
#define NKV   8
#define HD    64

// ---------------- static scratch ----------------
static __device__ float g_scale[4];
static __device__ float g_part[4 * 256];
static __device__ float g_q[S_LEN * HID];
static __device__ float g_k[S_LEN * NKV * HD];
static __device__ float g_v[S_LEN * NKV * HD];
static __device__ float g_att[S_LEN * HID];

// ---------------- absmean reduction (deterministic two-stage) ----------------
__global__ void absmean_partial(const float* __restrict__ w, int n, float* __restrict__ part) {
    __shared__ float red[256];
    float s = 0.f;
    for (int i = blockIdx.x * blockDim.x + threadIdx.x; i < n; i += gridDim.x * blockDim.x)
        s += fabsf(w[i]);
    red[threadIdx.x] = s;
    __syncthreads();
    for (int o = 128; o > 0; o >>= 1) {
        if (threadIdx.x < o) red[threadIdx.x] += red[threadIdx.x + o];
        __syncthreads();
    }
    if (threadIdx.x == 0) part[blockIdx.x] = red[0];
}

__global__ void absmean_final(const float* __restrict__ part, int n, float* __restrict__ scale) {
    __shared__ float red[256];
    red[threadIdx.x] = part[threadIdx.x];
    __syncthreads();
    for (int o = 128; o > 0; o >>= 1) {
        if (threadIdx.x < o) red[threadIdx.x] += red[threadIdx.x + o];
        __syncthreads();
    }
    if (threadIdx.x == 0) *scale = red[0] / (float)n + 1e-6f;
}

// ---------------- tf32 helpers ----------------
__device__ __forceinline__ unsigned f2tf32(float x) {
    unsigned r;
    asm("cvt.rna.tf32.f32 %0, %1;" : "=r"(r) : "f"(x));
    return r;
}

__device__ __forceinline__ void mma_tf32(float c[4], const unsigned a[4], const unsigned b[2]) {
    asm volatile(
        "mma.sync.aligned.m16n8k8.row.col.f32.tf32.tf32.f32 "
        "{%0,%1,%2,%3}, {%4,%5,%6,%7}, {%8,%9}, {%0,%1,%2,%3};"
        : "+f"(c[0]), "+f"(c[1]), "+f"(c[2]), "+f"(c[3])
        : "r"(a[0]), "r"(a[1]), "r"(a[2]), "r"(a[3]), "r"(b[0]), "r"(b[1]));
}

// ---------------- tensor-core GEMM: C = A * (scale * ternary(W))^T ----------------
// Ternary values are exact in tf32; scale applied in fp32 epilogue.
#define GBM 128
#define GBN 128
#define GBK 32
#define PAD 36

__global__ __launch_bounds__(256) void mma_gemm(const float* __restrict__ A,
                                                const float* __restrict__ W,
                                                float* __restrict__ C,
                                                int M, int N, int K,
                                                const float* __restrict__ scale_p) {
    __shared__ unsigned As[GBM][PAD];
    __shared__ unsigned Bs[GBN][PAD];

    const int tid = threadIdx.x;
    const float scale = *scale_p;
    const float inv = 1.f / scale;

    const int bm = blockIdx.y * GBM;
    const int bn = blockIdx.x * GBN;

    const int lr = tid >> 3;
    const int lc = (tid & 7) * 4;

    const int warp = tid >> 5, lane = tid & 31;
    const int wm = (warp & 1) * 64;
    const int wn = (warp >> 1) * 32;
    const int g = lane >> 2, tg = lane & 3;

    float c[4][4][4] = {};

    const float* Ap = A + (size_t)bm * K;
    const float* Wp = W + (size_t)bn * K;

    float4 fa[4], fb[4];
#pragma unroll
    for (int i = 0; i < 4; i++) {
        fa[i] = *(const float4*)(Ap + (size_t)(lr + 32 * i) * K + lc);
        fb[i] = *(const float4*)(Wp + (size_t)(lr + 32 * i) * K + lc);
    }

    for (int k0 = 0; k0 < K; k0 += GBK) {
        __syncthreads();
#pragma unroll
        for (int i = 0; i < 4; i++) {
            int r = lr + 32 * i;
            As[r][lc + 0] = f2tf32(fa[i].x);
            As[r][lc + 1] = f2tf32(fa[i].y);
            As[r][lc + 2] = f2tf32(fa[i].z);
            As[r][lc + 3] = f2tf32(fa[i].w);
            // exact ternary (representable in tf32)
            Bs[r][lc + 0] = f2tf32(rintf(fminf(fmaxf(fb[i].x * inv, -1.f), 1.f)));
            Bs[r][lc + 1] = f2tf32(rintf(fminf(fmaxf(fb[i].y * inv, -1.f), 1.f)));
            Bs[r][lc + 2] = f2tf32(rintf(fminf(fmaxf(fb[i].z * inv, -1.f), 1.f)));
            Bs[r][lc + 3] = f2tf32(rintf(fminf(fmaxf(fb[i].w * inv, -1.f), 1.f)));
        }
        __syncthreads();

        if (k0 + GBK < K) {
#pragma unroll
            for (int i = 0; i < 4; i++) {
                fa[i] = *(const float4*)(Ap + (size_t)(lr + 32 * i) * K + k0 + GBK + lc);
                fb[i] = *(const float4*)(Wp + (size_t)(lr + 32 * i) * K + k0 + GBK + lc);
            }
        }

#pragma unroll
        for (int ks = 0; ks < GBK; ks += 8) {
            unsigned a[4][4], b[4][2];
#pragma unroll
            for (int mt = 0; mt < 4; mt++) {
                int r = wm + mt * 16 + g;
                a[mt][0] = As[r][ks + tg];
                a[mt][1] = As[r + 8][ks + tg];
                a[mt][2] = As[r][ks + tg + 4];
                a[mt][3] = As[r + 8][ks + tg + 4];
            }
#pragma unroll
            for (int nt = 0; nt < 4; nt++) {
                int nr = wn + nt * 8 + g;
                b[nt][0] = Bs[nr][ks + tg];
                b[nt][1] = Bs[nr][ks + tg + 4];
            }
#pragma unroll
            for (int mt = 0; mt < 4; mt++)
#pragma unroll
                for (int nt = 0; nt < 4; nt++)
                    mma_tf32(c[mt][nt], a[mt], b[nt]);
        }
    }

#pragma unroll
    for (int mt = 0; mt < 4; mt++) {
#pragma unroll
        for (int nt = 0; nt < 4; nt++) {
            int row = bm + wm + mt * 16 + g;
            int col = bn + wn + nt * 8 + 2 * tg;
            *(float2*)(C + (size_t)row * N + col) =
                make_float2(c[mt][nt][0] * scale, c[mt][nt][1] * scale);
            *(float2*)(C + (size_t)(row + 8) * N + col) =
                make_float2(c[mt][nt][2] * scale, c[mt][nt][3] * scale);
        }
    }
}

// ---------------- RoPE (in place), x layout [S, nheads, 64] ----------------
__global__ void rope_kernel(float* __restrict__ x, const int* __restrict__ pos_ids, int nheads) {
    int idx = blockIdx.x * blockDim.x + threadIdx.x;
    int total = S_LEN * nheads * 32;
    if (idx >= total) return;
    int i = idx & 31;
    int h = (idx >> 5) % nheads;
    int s = idx / (32 * nheads);
    float pos = (float)pos_ids[s];
    float inv_freq = powf(10000.f, -(float)(2 * i) / 64.f);
    float ang = pos * inv_freq;
    float c = cosf(ang), sn = sinf(ang);
    float* base = x + (s * nheads + h) * HD;
    float x1 = base[i], x2 = base[i + 32];
    base[i]      = x1 * c - x2 * sn;
    base[i + 32] = x2 * c + x1 * sn;
}

// ---------------- tensor-core flash attention ----------------
// Block: 64 q-rows x 1 head. 4 warps, 16 rows/warp. KV tiles of 64.
// Ks[kv][d] pad 68, Vs[kv][d] pad 72 (transposed B indexing conflict-free),
// Ps[row][col] pad 68 (C-frag -> A-frag layout bridge).
#define KPAD 68
#define VPAD 72
#define FA_SMEM (64 * KPAD * 4 + 64 * VPAD * 4 + 64 * KPAD * 4 + 64 * 4)

__global__ __launch_bounds__(128) void flash_mma(const float* __restrict__ Q,
                                                 const float* __restrict__ Kg,
                                                 const float* __restrict__ Vg,
                                                 const float* __restrict__ mask,
                                                 float* __restrict__ O) {
    extern __shared__ unsigned sm[];
    unsigned (*Ks)[KPAD] = (unsigned(*)[KPAD])sm;
    unsigned (*Vs)[VPAD] = (unsigned(*)[VPAD])(sm + 64 * KPAD);
    unsigned (*Ps)[KPAD] = (unsigned(*)[KPAD])(sm + 64 * KPAD + 64 * VPAD);
    float* Msm = (float*)(sm + 64 * KPAD + 64 * VPAD + 64 * KPAD);

    const int tid = threadIdx.x;
    const int warp = tid >> 5, lane = tid & 31;
    const int g = lane >> 2, tg = lane & 3;
    const int wm = warp * 16;

    const int h = blockIdx.y;
    const int kvh = h >> 2;
    const int qbase = blockIdx.x * 64;

    // Q fragments in registers (scaled by 1/sqrt(64))
    unsigned qa[8][4];
    {
        const float* Qp = Q + (size_t)qbase * HID + h * HD;
        const int r0 = wm + g, r1 = wm + g + 8;
#pragma unroll
        for (int ks = 0; ks < 8; ks++) {
            qa[ks][0] = f2tf32(Qp[(size_t)r0 * HID + ks * 8 + tg] * 0.125f);
            qa[ks][1] = f2tf32(Qp[(size_t)r1 * HID + ks * 8 + tg] * 0.125f);
            qa[ks][2] = f2tf32(Qp[(size_t)r0 * HID + ks * 8 + tg + 4] * 0.125f);
            qa[ks][3] = f2tf32(Qp[(size_t)r1 * HID + ks * 8 + tg + 4] * 0.125f);
        }
    }

    float co[8][4] = {};
    float m_g = -1e30f, m_g8 = -1e30f, l_g = 0.f, l_g8 = 0.f;

    for (int t = 0; t < S_LEN; t += 64) {
        // cooperative K/V tile load (+ tf32 convert)
        for (int u = tid; u < 64 * 16; u += 128) {
            int r = u >> 4, c4 = (u & 15) * 4;
            const float4 kf = *(const float4*)(Kg + (size_t)(t + r) * (NKV * HD) + kvh * HD + c4);
            Ks[r][c4 + 0] = f2tf32(kf.x); Ks[r][c4 + 1] = f2tf32(kf.y);
            Ks[r][c4 + 2] = f2tf32(kf.z); Ks[r][c4 + 3] = f2tf32(kf.w);
            const float4 vf = *(const float4*)(Vg + (size_t)(t + r) * (NKV * HD) + kvh * HD + c4);
            Vs[r][c4 + 0] = f2tf32(vf.x); Vs[r][c4 + 1] = f2tf32(vf.y);
            Vs[r][c4 + 2] = f2tf32(vf.z); Vs[r][c4 + 3] = f2tf32(vf.w);
        }
        if (tid < 64) Msm[tid] = mask[t + tid];
        __syncthreads();

        // S = Q K^T
        float cs[8][4] = {};
#pragma unroll
        for (int ks = 0; ks < 8; ks++) {
#pragma unroll
            for (int nt = 0; nt < 8; nt++) {
                unsigned b[2];
                b[0] = Ks[nt * 8 + g][ks * 8 + tg];
                b[1] = Ks[nt * 8 + g][ks * 8 + tg + 4];
                mma_tf32(cs[nt], qa[ks], b);
            }
        }

        // mask + row max
        float mloc_g = -1e30f, mloc_g8 = -1e30f;
#pragma unroll
        for (int nt = 0; nt < 8; nt++) {
            float mk0 = Msm[nt * 8 + 2 * tg], mk1 = Msm[nt * 8 + 2 * tg + 1];
            cs[nt][0] += mk0; cs[nt][1] += mk1;
            cs[nt][2] += mk0; cs[nt][3] += mk1;
            mloc_g  = fmaxf(mloc_g,  fmaxf(cs[nt][0], cs[nt][1]));
            mloc_g8 = fmaxf(mloc_g8, fmaxf(cs[nt][2], cs[nt][3]));
        }
        mloc_g  = fmaxf(mloc_g,  __shfl_xor_sync(0xffffffff, mloc_g, 1));
        mloc_g  = fmaxf(mloc_g,  __shfl_xor_sync(0xffffffff, mloc_g, 2));
        mloc_g8 = fmaxf(mloc_g8, __shfl_xor_sync(0xffffffff, mloc_g8, 1));
        mloc_g8 = fmaxf(mloc_g8, __shfl_xor_sync(0xffffffff, mloc_g8, 2));

        float mn_g  = fmaxf(m_g,  mloc_g);
        float mn_g8 = fmaxf(m_g8, mloc_g8);
        float corr_g  = __expf(m_g - mn_g);
        float corr_g8 = __expf(m_g8 - mn_g8);

        float sum_g = 0.f, sum_g8 = 0.f;
#pragma unroll
        for (int nt = 0; nt < 8; nt++) {
            float p0 = __expf(cs[nt][0] - mn_g);
            float p1 = __expf(cs[nt][1] - mn_g);
            float p2 = __expf(cs[nt][2] - mn_g8);
            float p3 = __expf(cs[nt][3] - mn_g8);
            sum_g += p0 + p1; sum_g8 += p2 + p3;
            Ps[wm + g][nt * 8 + 2 * tg]     = f2tf32(p0);
            Ps[wm + g][nt * 8 + 2 * tg + 1] = f2tf32(p1);
            Ps[wm + g + 8][nt * 8 + 2 * tg]     = f2tf32(p2);
            Ps[wm + g + 8][nt * 8 + 2 * tg + 1] = f2tf32(p3);
            co[nt][0] *= corr_g;  co[nt][1] *= corr_g;
            co[nt][2] *= corr_g8; co[nt][3] *= corr_g8;
        }
        sum_g  += __shfl_xor_sync(0xffffffff, sum_g, 1);
        sum_g  += __shfl_xor_sync(0xffffffff, sum_g, 2);
        sum_g8 += __shfl_xor_sync(0xffffffff, sum_g8, 1);
        sum_g8 += __shfl_xor_sync(0xffffffff, sum_g8, 2);
        l_g  = l_g * corr_g + sum_g;
        l_g8 = l_g8 * corr_g8 + sum_g8;
        m_g = mn_g; m_g8 = mn_g8;
        __syncwarp();

        // O += P V
#pragma unroll
        for (int ks = 0; ks < 8; ks++) {
            unsigned a[4];
            a[0] = Ps[wm + g][ks * 8 + tg];
            a[1] = Ps[wm + g + 8][ks * 8 + tg];
            a[2] = Ps[wm + g][ks * 8 + tg + 4];
            a[3] = Ps[wm + g + 8][ks * 8 + tg + 4];
#pragma unroll
            for (int nt = 0; nt < 8; nt++) {
                unsigned b[2];
                b[0] = Vs[ks * 8 + tg][nt * 8 + g];
                b[1] = Vs[ks * 8 + tg + 4][nt * 8 + g];
                mma_tf32(co[nt], a, b);
            }
        }
        __syncthreads();
    }

    const float inv_g  = 1.f / l_g;
    const float inv_g8 = 1.f / l_g8;
    const int row0 = qbase + wm + g;
#pragma unroll
    for (int nt = 0; nt < 8; nt++) {
        int col = h * HD + nt * 8 + 2 * tg;
        *(float2*)(O + (size_t)row0 * HID + col) =
            make_float2(co[nt][0] * inv_g, co[nt][1] * inv_g);
        *(float2*)(O + (size_t)(row0 + 8) * HID + col) =
            make_float2(co[nt][2] * inv_g8, co[nt][3] * inv_g8);
    }
}

// ---------------- host launcher ----------------
extern "C" void kernel_launch(void* const* d_in, const int* in_sizes, int n_in,
                              void* d_out, int out_size) {
    const float* x    = (const float*)d_in[0];
    const float* mask = (const float*)d_in[1];
    const int*   pos  = (const int*)d_in[2];
    const float* wq   = (const float*)d_in[3];
    const float* wk   = (const float*)d_in[4];
    const float* wv   = (const float*)d_in[5];
    const float* wo   = (const float*)d_in[6];
    float* out = (float*)d_out;

    float *pscale, *ppart, *pq, *pk, *pv, *patt;
    cudaGetSymbolAddress((void**)&pscale, g_scale);
    cudaGetSymbolAddress((void**)&ppart,  g_part);
    cudaGetSymbolAddress((void**)&pq,     g_q);
    cudaGetSymbolAddress((void**)&pk,     g_k);
    cudaGetSymbolAddress((void**)&pv,     g_v);
    cudaGetSymbolAddress((void**)&patt,   g_att);

    static bool attr_set = false;
    if (!attr_set) {
        cudaFuncSetAttribute(flash_mma, cudaFuncAttributeMaxDynamicSharedMemorySize, FA_SMEM);
        attr_set = true;
    }

    const int n_big = HID * HID;
    const int n_kv  = NKV * HD * HID;

    absmean_partial<<<256, 256>>>(wq, n_big, ppart + 0 * 256);
    absmean_final<<<1, 256>>>(ppart + 0 * 256, n_big, pscale + 0);
    absmean_partial<<<256, 256>>>(wk, n_kv, ppart + 1 * 256);
    absmean_final<<<1, 256>>>(ppart + 1 * 256, n_kv, pscale + 1);
    absmean_partial<<<256, 256>>>(wv, n_kv, ppart + 2 * 256);
    absmean_final<<<1, 256>>>(ppart + 2 * 256, n_kv, pscale + 2);
    absmean_partial<<<256, 256>>>(wo, n_big, ppart + 3 * 256);
    absmean_final<<<1, 256>>>(ppart + 3 * 256, n_big, pscale + 3);

    mma_gemm<<<dim3(HID / GBN, S_LEN / GBM), 256>>>(x, wq, pq, S_LEN, HID, HID, pscale + 0);
    mma_gemm<<<dim3((NKV * HD) / GBN, S_LEN / GBM), 256>>>(x, wk, pk, S_LEN, NKV * HD, HID, pscale + 1);
    mma_gemm<<<dim3((NKV * HD) / GBN, S_LEN / GBM), 256>>>(x, wv, pv, S_LEN, NKV * HD, HID, pscale + 2);

    rope_kernel<<<(S_LEN * NH * 32 + 255) / 256, 256>>>(pq, pos, NH);
    rope_kernel<<<(S_LEN * NKV * 32 + 255) / 256, 256>>>(pk, pos, NKV);

    flash_mma<<<dim3(S_LEN / 64, NH), 128, FA_SMEM>>>(pq, pk, pv, mask, patt);

    mma_gemm<<<dim3(HID / GBN, S_LEN / GBM), 256>>>(patt, wo, out, S_LEN, HID, HID, pscale + 3);
}

// round 4
// speedup vs baseline: 3.7033x; 1.1056x over previous
#include <cuda_runtime.h>
#include <cuda_bf16.h>
#include <math.h>

#define S_LEN 2048
#define HID   2048
#define NH    32
#define NKV   8
#define HD    64

// ---------------- static scratch ----------------
static __device__ float g_scale[4];
static __device__ float g_part[4 * 256];
static __device__ float g_x[S_LEN * HID];          // tf32-rounded activations
static __device__ float g_wq[HID * HID];           // exact ternary
static __device__ float g_wk[NKV * HD * HID];
static __device__ float g_wv[NKV * HD * HID];
static __device__ float g_wo[HID * HID];
static __device__ float g_q[S_LEN * HID];
static __device__ float g_k[S_LEN * NKV * HD];
static __device__ float g_v[S_LEN * NKV * HD];
static __device__ float g_att[S_LEN * HID];

// ---------------- helpers ----------------
__device__ __forceinline__ unsigned f2tf32(float x) {
    unsigned r;
    asm("cvt.rna.tf32.f32 %0, %1;" : "=r"(r) : "f"(x));
    return r;
}

__device__ __forceinline__ void mma_tf32(float c[4], const unsigned a[4], const unsigned b[2]) {
    asm volatile(
        "mma.sync.aligned.m16n8k8.row.col.f32.tf32.tf32.f32 "
        "{%0,%1,%2,%3}, {%4,%5,%6,%7}, {%8,%9}, {%0,%1,%2,%3};"
        : "+f"(c[0]), "+f"(c[1]), "+f"(c[2]), "+f"(c[3])
        : "r"(a[0]), "r"(a[1]), "r"(a[2]), "r"(a[3]), "r"(b[0]), "r"(b[1]));
}

__device__ __forceinline__ void cp_async16(void* smem_dst, const void* gptr) {
    unsigned s = (unsigned)__cvta_generic_to_shared(smem_dst);
    asm volatile("cp.async.cg.shared.global [%0], [%1], 16;" :: "r"(s), "l"(gptr));
}
__device__ __forceinline__ void cp_commit() { asm volatile("cp.async.commit_group;"); }
template <int N>
__device__ __forceinline__ void cp_wait() { asm volatile("cp.async.wait_group %0;" :: "n"(N)); }

// ---------------- fused absmean (deterministic two-stage) ----------------
__global__ void absmean_all_partial(const float* __restrict__ wq, const float* __restrict__ wk,
                                    const float* __restrict__ wv, const float* __restrict__ wo,
                                    float* __restrict__ part) {
    __shared__ float red[256];
    int t = blockIdx.y;
    const float* w = t == 0 ? wq : t == 1 ? wk : t == 2 ? wv : wo;
    int n = (t == 0 || t == 3) ? HID * HID : NKV * HD * HID;
    float s = 0.f;
    for (int i = blockIdx.x * blockDim.x + threadIdx.x; i < n; i += gridDim.x * blockDim.x)
        s += fabsf(w[i]);
    red[threadIdx.x] = s;
    __syncthreads();
    for (int o = 128; o > 0; o >>= 1) {
        if (threadIdx.x < o) red[threadIdx.x] += red[threadIdx.x + o];
        __syncthreads();
    }
    if (threadIdx.x == 0) part[t * 256 + blockIdx.x] = red[0];
}

__global__ void absmean_all_final(const float* __restrict__ part, float* __restrict__ scale) {
    __shared__ float red[256];
    int t = blockIdx.x;
    int n = (t == 0 || t == 3) ? HID * HID : NKV * HD * HID;
    red[threadIdx.x] = part[t * 256 + threadIdx.x];
    __syncthreads();
    for (int o = 128; o > 0; o >>= 1) {
        if (threadIdx.x < o) red[threadIdx.x] += red[threadIdx.x + o];
        __syncthreads();
    }
    if (threadIdx.x == 0) scale[t] = red[0] / (float)n + 1e-6f;
}

// ---------------- fused ternary quantization (exact -1/0/1 floats) ----------------
__global__ void quantize_all(const float* __restrict__ wq, const float* __restrict__ wk,
                             const float* __restrict__ wv, const float* __restrict__ wo,
                             float* __restrict__ oq, float* __restrict__ ok,
                             float* __restrict__ ov, float* __restrict__ oo,
                             const float* __restrict__ scales) {
    int t = blockIdx.y;
    const float4* w = (const float4*)(t == 0 ? wq : t == 1 ? wk : t == 2 ? wv : wo);
    float4* o = (float4*)(t == 0 ? oq : t == 1 ? ok : t == 2 ? ov : oo);
    int n4 = ((t == 0 || t == 3) ? HID * HID : NKV * HD * HID) >> 2;
    float inv = 1.f / scales[t];
    for (int i = blockIdx.x * blockDim.x + threadIdx.x; i < n4; i += gridDim.x * blockDim.x) {
        float4 v = w[i];
        v.x = rintf(fminf(fmaxf(v.x * inv, -1.f), 1.f));
        v.y = rintf(fminf(fmaxf(v.y * inv, -1.f), 1.f));
        v.z = rintf(fminf(fmaxf(v.z * inv, -1.f), 1.f));
        v.w = rintf(fminf(fmaxf(v.w * inv, -1.f), 1.f));
        o[i] = v;
    }
}

// ---------------- round activations to tf32-representable fp32 ----------------
__global__ void round_x(const float* __restrict__ in, float* __restrict__ out, int n4) {
    int i = blockIdx.x * blockDim.x + threadIdx.x;
    if (i >= n4) return;
    float4 v = ((const float4*)in)[i];
    v.x = __uint_as_float(f2tf32(v.x));
    v.y = __uint_as_float(f2tf32(v.y));
    v.z = __uint_as_float(f2tf32(v.z));
    v.w = __uint_as_float(f2tf32(v.w));
    ((float4*)out)[i] = v;
}

// ---------------- 3-stage cp.async tf32 GEMM: C = A * W^T * scale ----------------
// A and W pre-rounded to tf32-representable fp32 -> raw bits feed the mma.
#define GBM 128
#define GBN 128
#define GBK 32
#define PAD 36
#define STAGES 3
#define GEMM_SMEM (STAGES * 2 * GBM * PAD * 4)

template <bool ROUND>
__global__ __launch_bounds__(256) void gemm_pipe(const float* __restrict__ A,
                                                 const float* __restrict__ W,
                                                 float* __restrict__ C,
                                                 int N, int K,
                                                 const float* __restrict__ scale_p) {
    extern __shared__ unsigned sm_g[];
    unsigned (*As)[GBM][PAD] = (unsigned(*)[GBM][PAD])sm_g;
    unsigned (*Bs)[GBM][PAD] = (unsigned(*)[GBM][PAD])(sm_g + STAGES * GBM * PAD);

    const int tid = threadIdx.x;
    const float scale = *scale_p;
    const int bm = blockIdx.y * GBM;
    const int bn = blockIdx.x * GBN;

    const int lr = tid >> 3;          // 0..31
    const int lc = (tid & 7) * 4;     // 0,4,...,28

    const int warp = tid >> 5, lane = tid & 31;
    const int wm = (warp & 1) * 64;
    const int wn = (warp >> 1) * 32;
    const int g = lane >> 2, tg = lane & 3;

    const float* Ap = A + (size_t)bm * K;
    const float* Wp = W + (size_t)bn * K;

    float c[4][4][4] = {};

    const int ntiles = K / GBK;

    auto load_tile = [&](int stage, int k0) {
#pragma unroll
        for (int i = 0; i < 4; i++) {
            int r = lr + 32 * i;
            cp_async16(&As[stage][r][lc], Ap + (size_t)r * K + k0 + lc);
            cp_async16(&Bs[stage][r][lc], Wp + (size_t)r * K + k0 + lc);
        }
    };

#pragma unroll
    for (int s = 0; s < STAGES - 1; s++) {
        load_tile(s, s * GBK);
        cp_commit();
    }

    for (int kt = 0; kt < ntiles; kt++) {
        cp_wait<STAGES - 2>();
        __syncthreads();

        int kn = kt + STAGES - 1;
        if (kn < ntiles) load_tile(kn % STAGES, kn * GBK);
        cp_commit();

        const int st = kt % STAGES;
#pragma unroll
        for (int ks = 0; ks < GBK; ks += 8) {
            unsigned a[4][4], b[4][2];
#pragma unroll
            for (int mt = 0; mt < 4; mt++) {
                int r = wm + mt * 16 + g;
                a[mt][0] = As[st][r][ks + tg];
                a[mt][1] = As[st][r + 8][ks + tg];
                a[mt][2] = As[st][r][ks + tg + 4];
                a[mt][3] = As[st][r + 8][ks + tg + 4];
            }
#pragma unroll
            for (int nt = 0; nt < 4; nt++) {
                int nr = wn + nt * 8 + g;
                b[nt][0] = Bs[st][nr][ks + tg];
                b[nt][1] = Bs[st][nr][ks + tg + 4];
            }
#pragma unroll
            for (int mt = 0; mt < 4; mt++)
#pragma unroll
                for (int nt = 0; nt < 4; nt++)
                    mma_tf32(c[mt][nt], a[mt], b[nt]);
        }
        __syncthreads();
    }

#pragma unroll
    for (int mt = 0; mt < 4; mt++) {
#pragma unroll
        for (int nt = 0; nt < 4; nt++) {
            int row = bm + wm + mt * 16 + g;
            int col = bn + wn + nt * 8 + 2 * tg;
            float v0 = c[mt][nt][0] * scale, v1 = c[mt][nt][1] * scale;
            float v2 = c[mt][nt][2] * scale, v3 = c[mt][nt][3] * scale;
            if (ROUND) {
                v0 = __uint_as_float(f2tf32(v0)); v1 = __uint_as_float(f2tf32(v1));
                v2 = __uint_as_float(f2tf32(v2)); v3 = __uint_as_float(f2tf32(v3));
            }
            *(float2*)(C + (size_t)row * N + col) = make_float2(v0, v1);
            *(float2*)(C + (size_t)(row + 8) * N + col) = make_float2(v2, v3);
        }
    }
}

// ---------------- RoPE (in place, emits tf32-rounded values) ----------------
__global__ void rope_kernel(float* __restrict__ x, const int* __restrict__ pos_ids, int nheads) {
    int idx = blockIdx.x * blockDim.x + threadIdx.x;
    int total = S_LEN * nheads * 32;
    if (idx >= total) return;
    int i = idx & 31;
    int h = (idx >> 5) % nheads;
    int s = idx / (32 * nheads);
    float pos = (float)pos_ids[s];
    float inv_freq = powf(10000.f, -(float)(2 * i) / 64.f);
    float ang = pos * inv_freq;
    float c = cosf(ang), sn = sinf(ang);
    float* base = x + (s * nheads + h) * HD;
    float x1 = base[i], x2 = base[i + 32];
    base[i]      = __uint_as_float(f2tf32(x1 * c - x2 * sn));
    base[i + 32] = __uint_as_float(f2tf32(x2 * c + x1 * sn));
}

// ---------------- tensor-core flash attention (cp.async double-buffered K/V) ----------------
#define KPAD 68
#define VPAD 72
#define FA_SMEM ((2 * 64 * KPAD + 2 * 64 * VPAD + 64 * KPAD) * 4)

__global__ __launch_bounds__(128) void flash_mma(const float* __restrict__ Q,
                                                 const float* __restrict__ Kg,
                                                 const float* __restrict__ Vg,
                                                 const float* __restrict__ mask,
                                                 float* __restrict__ O) {
    extern __shared__ unsigned sm[];
    unsigned (*Ks)[64][KPAD] = (unsigned(*)[64][KPAD])sm;
    unsigned (*Vs)[64][VPAD] = (unsigned(*)[64][VPAD])(sm + 2 * 64 * KPAD);
    unsigned (*Ps)[KPAD] = (unsigned(*)[KPAD])(sm + 2 * 64 * KPAD + 2 * 64 * VPAD);

    const int tid = threadIdx.x;
    const int warp = tid >> 5, lane = tid & 31;
    const int g = lane >> 2, tg = lane & 3;
    const int wm = warp * 16;

    const int h = blockIdx.y;
    const int kvh = h >> 2;
    const int qbase = blockIdx.x * 64;

    // K/V tiles: pre-rounded in gmem -> raw bit copies
    auto load_tiles = [&](int buf, int t) {
#pragma unroll
        for (int u = 0; u < 8; u++) {
            int slot = tid + u * 128;           // 0..1023
            int r = slot >> 4, c4 = (slot & 15) * 4;
            cp_async16(&Ks[buf][r][c4], Kg + (size_t)(t + r) * (NKV * HD) + kvh * HD + c4);
            cp_async16(&Vs[buf][r][c4], Vg + (size_t)(t + r) * (NKV * HD) + kvh * HD + c4);
        }
    };

    // Q fragments (pre-rounded; *0.125 is exact in tf32)
    unsigned qa[8][4];
    {
        const float* Qp = Q + (size_t)qbase * HID + h * HD;
        const int r0 = wm + g, r1 = wm + g + 8;
#pragma unroll
        for (int ks = 0; ks < 8; ks++) {
            qa[ks][0] = __float_as_uint(Qp[(size_t)r0 * HID + ks * 8 + tg] * 0.125f);
            qa[ks][1] = __float_as_uint(Qp[(size_t)r1 * HID + ks * 8 + tg] * 0.125f);
            qa[ks][2] = __float_as_uint(Qp[(size_t)r0 * HID + ks * 8 + tg + 4] * 0.125f);
            qa[ks][3] = __float_as_uint(Qp[(size_t)r1 * HID + ks * 8 + tg + 4] * 0.125f);
        }
    }

    float co[8][4] = {};
    float m_g = -1e30f, m_g8 = -1e30f, l_g = 0.f, l_g8 = 0.f;

    load_tiles(0, 0);
    cp_commit();

    for (int ti = 0; ti < S_LEN / 64; ti++) {
        const int t = ti * 64;
        if (ti + 1 < S_LEN / 64) load_tiles((ti + 1) & 1, t + 64);
        cp_commit();
        cp_wait<1>();
        __syncthreads();

        const int buf = ti & 1;

        // S = Q K^T
        float cs[8][4] = {};
#pragma unroll
        for (int ks = 0; ks < 8; ks++) {
#pragma unroll
            for (int nt = 0; nt < 8; nt++) {
                unsigned b[2];
                b[0] = Ks[buf][nt * 8 + g][ks * 8 + tg];
                b[1] = Ks[buf][nt * 8 + g][ks * 8 + tg + 4];
                mma_tf32(cs[nt], qa[ks], b);
            }
        }

        float mloc_g = -1e30f, mloc_g8 = -1e30f;
#pragma unroll
        for (int nt = 0; nt < 8; nt++) {
            float mk0 = __ldg(mask + t + nt * 8 + 2 * tg);
            float mk1 = __ldg(mask + t + nt * 8 + 2 * tg + 1);
            cs[nt][0] += mk0; cs[nt][1] += mk1;
            cs[nt][2] += mk0; cs[nt][3] += mk1;
            mloc_g  = fmaxf(mloc_g,  fmaxf(cs[nt][0], cs[nt][1]));
            mloc_g8 = fmaxf(mloc_g8, fmaxf(cs[nt][2], cs[nt][3]));
        }
        mloc_g  = fmaxf(mloc_g,  __shfl_xor_sync(0xffffffff, mloc_g, 1));
        mloc_g  = fmaxf(mloc_g,  __shfl_xor_sync(0xffffffff, mloc_g, 2));
        mloc_g8 = fmaxf(mloc_g8, __shfl_xor_sync(0xffffffff, mloc_g8, 1));
        mloc_g8 = fmaxf(mloc_g8, __shfl_xor_sync(0xffffffff, mloc_g8, 2));

        float mn_g  = fmaxf(m_g,  mloc_g);
        float mn_g8 = fmaxf(m_g8, mloc_g8);
        float corr_g  = __expf(m_g - mn_g);
        float corr_g8 = __expf(m_g8 - mn_g8);

        float sum_g = 0.f, sum_g8 = 0.f;
#pragma unroll
        for (int nt = 0; nt < 8; nt++) {
            float p0 = __expf(cs[nt][0] - mn_g);
            float p1 = __expf(cs[nt][1] - mn_g);
            float p2 = __expf(cs[nt][2] - mn_g8);
            float p3 = __expf(cs[nt][3] - mn_g8);
            sum_g += p0 + p1; sum_g8 += p2 + p3;
            Ps[wm + g][nt * 8 + 2 * tg]         = f2tf32(p0);
            Ps[wm + g][nt * 8 + 2 * tg + 1]     = f2tf32(p1);
            Ps[wm + g + 8][nt * 8 + 2 * tg]     = f2tf32(p2);
            Ps[wm + g + 8][nt * 8 + 2 * tg + 1] = f2tf32(p3);
            co[nt][0] *= corr_g;  co[nt][1] *= corr_g;
            co[nt][2] *= corr_g8; co[nt][3] *= corr_g8;
        }
        sum_g  += __shfl_xor_sync(0xffffffff, sum_g, 1);
        sum_g  += __shfl_xor_sync(0xffffffff, sum_g, 2);
        sum_g8 += __shfl_xor_sync(0xffffffff, sum_g8, 1);
        sum_g8 += __shfl_xor_sync(0xffffffff, sum_g8, 2);
        l_g  = l_g * corr_g + sum_g;
        l_g8 = l_g8 * corr_g8 + sum_g8;
        m_g = mn_g; m_g8 = mn_g8;
        __syncwarp();

        // O += P V
#pragma unroll
        for (int ks = 0; ks < 8; ks++) {
            unsigned a[4];
            a[0] = Ps[wm + g][ks * 8 + tg];
            a[1] = Ps[wm + g + 8][ks * 8 + tg];
            a[2] = Ps[wm + g][ks * 8 + tg + 4];
            a[3] = Ps[wm + g + 8][ks * 8 + tg + 4];
#pragma unroll
            for (int nt = 0; nt < 8; nt++) {
                unsigned b[2];
                b[0] = Vs[buf][ks * 8 + tg][nt * 8 + g];
                b[1] = Vs[buf][ks * 8 + tg + 4][nt * 8 + g];
                mma_tf32(co[nt], a, b);
            }
        }
        __syncthreads();
    }

    const float inv_g  = 1.f / l_g;
    const float inv_g8 = 1.f / l_g8;
    const int row0 = qbase + wm + g;
#pragma unroll
    for (int nt = 0; nt < 8; nt++) {
        int col = h * HD + nt * 8 + 2 * tg;
        *(float2*)(O + (size_t)row0 * HID + col) =
            make_float2(__uint_as_float(f2tf32(co[nt][0] * inv_g)),
                        __uint_as_float(f2tf32(co[nt][1] * inv_g)));
        *(float2*)(O + (size_t)(row0 + 8) * HID + col) =
            make_float2(__uint_as_float(f2tf32(co[nt][2] * inv_g8)),
                        __uint_as_float(f2tf32(co[nt][3] * inv_g8)));
    }
}

// ---------------- host launcher ----------------
extern "C" void kernel_launch(void* const* d_in, const int* in_sizes, int n_in,
                              void* d_out, int out_size) {
    const float* x    = (const float*)d_in[0];
    const float* mask = (const float*)d_in[1];
    const int*   pos  = (const int*)d_in[2];
    const float* wq   = (const float*)d_in[3];
    const float* wk   = (const float*)d_in[4];
    const float* wv   = (const float*)d_in[5];
    const float* wo   = (const float*)d_in[6];
    float* out = (float*)d_out;

    float *pscale, *ppart, *px, *pwq, *pwk, *pwv, *pwo, *pq, *pk, *pv, *patt;
    cudaGetSymbolAddress((void**)&pscale, g_scale);
    cudaGetSymbolAddress((void**)&ppart,  g_part);
    cudaGetSymbolAddress((void**)&px,     g_x);
    cudaGetSymbolAddress((void**)&pwq,    g_wq);
    cudaGetSymbolAddress((void**)&pwk,    g_wk);
    cudaGetSymbolAddress((void**)&pwv,    g_wv);
    cudaGetSymbolAddress((void**)&pwo,    g_wo);
    cudaGetSymbolAddress((void**)&pq,     g_q);
    cudaGetSymbolAddress((void**)&pk,     g_k);
    cudaGetSymbolAddress((void**)&pv,     g_v);
    cudaGetSymbolAddress((void**)&patt,   g_att);

    cudaFuncSetAttribute(gemm_pipe<true>,  cudaFuncAttributeMaxDynamicSharedMemorySize, GEMM_SMEM);
    cudaFuncSetAttribute(gemm_pipe<false>, cudaFuncAttributeMaxDynamicSharedMemorySize, GEMM_SMEM);
    cudaFuncSetAttribute(flash_mma, cudaFuncAttributeMaxDynamicSharedMemorySize, FA_SMEM);

    // scales
    absmean_all_partial<<<dim3(256, 4), 256>>>(wq, wk, wv, wo, ppart);
    absmean_all_final<<<4, 256>>>(ppart, pscale);

    // pre-passes: exact ternary weights + tf32-rounded activations
    quantize_all<<<dim3(1024, 4), 256>>>(wq, wk, wv, wo, pwq, pwk, pwv, pwo, pscale);
    round_x<<<(S_LEN * HID / 4 + 255) / 256, 256>>>(x, px, S_LEN * HID / 4);

    // projections (tensor cores, zero-conversion pipelined tf32)
    gemm_pipe<true><<<dim3(HID / GBN, S_LEN / GBM), 256, GEMM_SMEM>>>(px, pwq, pq, HID, HID, pscale + 0);
    gemm_pipe<true><<<dim3((NKV * HD) / GBN, S_LEN / GBM), 256, GEMM_SMEM>>>(px, pwk, pk, NKV * HD, HID, pscale + 1);
    gemm_pipe<true><<<dim3((NKV * HD) / GBN, S_LEN / GBM), 256, GEMM_SMEM>>>(px, pwv, pv, NKV * HD, HID, pscale + 2);

    rope_kernel<<<(S_LEN * NH * 32 + 255) / 256, 256>>>(pq, pos, NH);
    rope_kernel<<<(S_LEN * NKV * 32 + 255) / 256, 256>>>(pk, pos, NKV);

    flash_mma<<<dim3(S_LEN / 64, NH), 128, FA_SMEM>>>(pq, pk, pv, mask, patt);

    gemm_pipe<false><<<dim3(HID / GBN, S_LEN / GBM), 256, GEMM_SMEM>>>(patt, pwo, out, HID, HID, pscale + 3);
}

// round 7
// speedup vs baseline: 4.6979x; 1.2686x over previous
#include <cuda_runtime.h>
#include <cuda_fp16.h>
#include <math.h>

#define S_LEN 2048
#define HID   2048
#define NH    32
#define NKV   8
#define HD    64

// ---------------- static scratch ----------------
static __device__ float  g_scale[4];
static __device__ float  g_part[4 * 256];
static __device__ __half g_xh[S_LEN * HID];          // fp16 activations
static __device__ __half g_wq[HID * HID];            // exact ternary fp16
static __device__ __half g_wk[NKV * HD * HID];
static __device__ __half g_wv[NKV * HD * HID];
static __device__ __half g_wo[HID * HID];
static __device__ float  g_q[S_LEN * HID];
static __device__ float  g_k[S_LEN * NKV * HD];
static __device__ float  g_v[S_LEN * NKV * HD];
static __device__ __half g_atth[S_LEN * HID];        // attention out (fp16)

// ---------------- helpers ----------------
__device__ __forceinline__ unsigned f2tf32(float x) {
    unsigned r;
    asm("cvt.rna.tf32.f32 %0, %1;" : "=r"(r) : "f"(x));
    return r;
}

__device__ __forceinline__ unsigned pack_half2(float lo, float hi) {
    __half2 h = __floats2half2_rn(lo, hi);
    return *(unsigned*)&h;
}

__device__ __forceinline__ void mma_tf32(float c[4], const unsigned a[4], const unsigned b[2]) {
    asm volatile(
        "mma.sync.aligned.m16n8k8.row.col.f32.tf32.tf32.f32 "
        "{%0,%1,%2,%3}, {%4,%5,%6,%7}, {%8,%9}, {%0,%1,%2,%3};"
        : "+f"(c[0]), "+f"(c[1]), "+f"(c[2]), "+f"(c[3])
        : "r"(a[0]), "r"(a[1]), "r"(a[2]), "r"(a[3]), "r"(b[0]), "r"(b[1]));
}

__device__ __forceinline__ void mma_f16(float c[4], const unsigned a[4], const unsigned b[2]) {
    asm volatile(
        "mma.sync.aligned.m16n8k16.row.col.f32.f16.f16.f32 "
        "{%0,%1,%2,%3}, {%4,%5,%6,%7}, {%8,%9}, {%0,%1,%2,%3};"
        : "+f"(c[0]), "+f"(c[1]), "+f"(c[2]), "+f"(c[3])
        : "r"(a[0]), "r"(a[1]), "r"(a[2]), "r"(a[3]), "r"(b[0]), "r"(b[1]));
}

__device__ __forceinline__ void cp_async16(void* smem_dst, const void* gptr) {
    unsigned s = (unsigned)__cvta_generic_to_shared(smem_dst);
    asm volatile("cp.async.cg.shared.global [%0], [%1], 16;" :: "r"(s), "l"(gptr));
}
__device__ __forceinline__ void cp_commit() { asm volatile("cp.async.commit_group;"); }
template <int N>
__device__ __forceinline__ void cp_wait() { asm volatile("cp.async.wait_group %0;" :: "n"(N)); }

// ---------------- fused absmean (deterministic two-stage) ----------------
__global__ void absmean_all_partial(const float* __restrict__ wq, const float* __restrict__ wk,
                                    const float* __restrict__ wv, const float* __restrict__ wo,
                                    float* __restrict__ part) {
    __shared__ float red[256];
    int t = blockIdx.y;
    const float* w = t == 0 ? wq : t == 1 ? wk : t == 2 ? wv : wo;
    int n = (t == 0 || t == 3) ? HID * HID : NKV * HD * HID;
    float s = 0.f;
    for (int i = blockIdx.x * blockDim.x + threadIdx.x; i < n; i += gridDim.x * blockDim.x)
        s += fabsf(w[i]);
    red[threadIdx.x] = s;
    __syncthreads();
    for (int o = 128; o > 0; o >>= 1) {
        if (threadIdx.x < o) red[threadIdx.x] += red[threadIdx.x + o];
        __syncthreads();
    }
    if (threadIdx.x == 0) part[t * 256 + blockIdx.x] = red[0];
}

__global__ void absmean_all_final(const float* __restrict__ part, float* __restrict__ scale) {
    __shared__ float red[256];
    int t = blockIdx.x;
    int n = (t == 0 || t == 3) ? HID * HID : NKV * HD * HID;
    red[threadIdx.x] = part[t * 256 + threadIdx.x];
    __syncthreads();
    for (int o = 128; o > 0; o >>= 1) {
        if (threadIdx.x < o) red[threadIdx.x] += red[threadIdx.x + o];
        __syncthreads();
    }
    if (threadIdx.x == 0) scale[t] = red[0] / (float)n + 1e-6f;
}

// ---------------- ternary quantization -> exact fp16 {-1,0,1} ----------------
__global__ void quantize_all_h(const float* __restrict__ wq, const float* __restrict__ wk,
                               const float* __restrict__ wv, const float* __restrict__ wo,
                               __half* __restrict__ oq, __half* __restrict__ ok,
                               __half* __restrict__ ov, __half* __restrict__ oo,
                               const float* __restrict__ scales) {
    int t = blockIdx.y;
    const float4* w = (const float4*)(t == 0 ? wq : t == 1 ? wk : t == 2 ? wv : wo);
    __half* o = (t == 0 ? oq : t == 1 ? ok : t == 2 ? ov : oo);
    int n4 = ((t == 0 || t == 3) ? HID * HID : NKV * HD * HID) >> 2;
    float inv = 1.f / scales[t];
    for (int i = blockIdx.x * blockDim.x + threadIdx.x; i < n4; i += gridDim.x * blockDim.x) {
        float4 v = w[i];
        unsigned u0 = pack_half2(rintf(fminf(fmaxf(v.x * inv, -1.f), 1.f)),
                                 rintf(fminf(fmaxf(v.y * inv, -1.f), 1.f)));
        unsigned u1 = pack_half2(rintf(fminf(fmaxf(v.z * inv, -1.f), 1.f)),
                                 rintf(fminf(fmaxf(v.w * inv, -1.f), 1.f)));
        ((uint2*)o)[i] = make_uint2(u0, u1);
    }
}

// ---------------- fp32 -> fp16 activations ----------------
__global__ void cvt_x_half(const float* __restrict__ in, __half* __restrict__ out, int n4) {
    int i = blockIdx.x * blockDim.x + threadIdx.x;
    if (i >= n4) return;
    float4 v = ((const float4*)in)[i];
    ((uint2*)out)[i] = make_uint2(pack_half2(v.x, v.y), pack_half2(v.z, v.w));
}

// ---------------- fp16 tensor-core GEMM: C[M,N] = A[M,K] * W[N,K]^T * scale ----------------
// Block 128x128x32(halves). 8 warps 2(M)x4(N), warp tile 64x32. 3-stage cp.async.
// PADH=40 halves row stride -> fragment loads conflict-free (20g+tg distinct mod 32).
#define GBM 128
#define GBN 128
#define GBKH 32
#define PADH 40
#define STAGES 3
#define HGEMM_SMEM (STAGES * 2 * GBM * PADH * 2)

template <bool ROUND>
__global__ __launch_bounds__(256) void hgemm_pipe(const __half* __restrict__ A,
                                                  const __half* __restrict__ W,
                                                  float* __restrict__ C,
                                                  int N, int K,
                                                  const float* __restrict__ scale_p) {
    extern __shared__ __half hsm[];
    __half* Ah = hsm;                                // STAGES * GBM*PADH
    __half* Bh = hsm + STAGES * GBM * PADH;

    const int tid = threadIdx.x;
    const float scale = *scale_p;
    const int bm = blockIdx.y * GBM;
    const int bn = blockIdx.x * GBN;

    const int warp = tid >> 5, lane = tid & 31;
    const int wm = (warp & 1) * 64;
    const int wn = (warp >> 1) * 32;
    const int g = lane >> 2, tg = lane & 3;

    const __half* Ap = A + (size_t)bm * K;
    const __half* Wp = W + (size_t)bn * K;

    float c[4][4][4] = {};
    const int ntiles = K / GBKH;

    auto load_tile = [&](int stage, int k0) {
#pragma unroll
        for (int i = 0; i < 2; i++) {
            int ch = tid + i * 256;              // 0..511
            int r = ch >> 2, c8 = (ch & 3) * 8;  // row, 8-half chunk
            cp_async16(Ah + stage * GBM * PADH + r * PADH + c8, Ap + (size_t)r * K + k0 + c8);
            cp_async16(Bh + stage * GBM * PADH + r * PADH + c8, Wp + (size_t)r * K + k0 + c8);
        }
    };

#pragma unroll
    for (int s = 0; s < STAGES - 1; s++) {
        load_tile(s, s * GBKH);
        cp_commit();
    }

    for (int kt = 0; kt < ntiles; kt++) {
        cp_wait<STAGES - 2>();
        __syncthreads();

        int kn = kt + STAGES - 1;
        if (kn < ntiles) load_tile(kn % STAGES, kn * GBKH);
        cp_commit();

        const __half* As = Ah + (kt % STAGES) * GBM * PADH;
        const __half* Bs = Bh + (kt % STAGES) * GBM * PADH;

#pragma unroll
        for (int ks = 0; ks < GBKH; ks += 16) {
            unsigned a[4][4], b[4][2];
#pragma unroll
            for (int mt = 0; mt < 4; mt++) {
                int r = wm + mt * 16 + g;
                a[mt][0] = *(const unsigned*)(As + r * PADH + ks + 2 * tg);
                a[mt][1] = *(const unsigned*)(As + (r + 8) * PADH + ks + 2 * tg);
                a[mt][2] = *(const unsigned*)(As + r * PADH + ks + 2 * tg + 8);
                a[mt][3] = *(const unsigned*)(As + (r + 8) * PADH + ks + 2 * tg + 8);
            }
#pragma unroll
            for (int nt = 0; nt < 4; nt++) {
                int nr = wn + nt * 8 + g;
                b[nt][0] = *(const unsigned*)(Bs + nr * PADH + ks + 2 * tg);
                b[nt][1] = *(const unsigned*)(Bs + nr * PADH + ks + 2 * tg + 8);
            }
#pragma unroll
            for (int mt = 0; mt < 4; mt++)
#pragma unroll
                for (int nt = 0; nt < 4; nt++)
                    mma_f16(c[mt][nt], a[mt], b[nt]);
        }
        __syncthreads();
    }

#pragma unroll
    for (int mt = 0; mt < 4; mt++) {
#pragma unroll
        for (int nt = 0; nt < 4; nt++) {
            int row = bm + wm + mt * 16 + g;
            int col = bn + wn + nt * 8 + 2 * tg;
            float v0 = c[mt][nt][0] * scale, v1 = c[mt][nt][1] * scale;
            float v2 = c[mt][nt][2] * scale, v3 = c[mt][nt][3] * scale;
            if (ROUND) {
                v0 = __uint_as_float(f2tf32(v0)); v1 = __uint_as_float(f2tf32(v1));
                v2 = __uint_as_float(f2tf32(v2)); v3 = __uint_as_float(f2tf32(v3));
            }
            *(float2*)(C + (size_t)row * N + col) = make_float2(v0, v1);
            *(float2*)(C + (size_t)(row + 8) * N + col) = make_float2(v2, v3);
        }
    }
}

// ---------------- RoPE (in place, emits tf32-rounded values) ----------------
__global__ void rope_kernel(float* __restrict__ x, const int* __restrict__ pos_ids, int nheads) {
    int idx = blockIdx.x * blockDim.x + threadIdx.x;
    int total = S_LEN * nheads * 32;
    if (idx >= total) return;
    int i = idx & 31;
    int h = (idx >> 5) % nheads;
    int s = idx / (32 * nheads);
    float pos = (float)pos_ids[s];
    float inv_freq = powf(10000.f, -(float)(2 * i) / 64.f);
    float ang = pos * inv_freq;
    float c = cosf(ang), sn = sinf(ang);
    float* base = x + (s * nheads + h) * HD;
    float x1 = base[i], x2 = base[i + 32];
    base[i]      = __uint_as_float(f2tf32(x1 * c - x2 * sn));
    base[i + 32] = __uint_as_float(f2tf32(x2 * c + x1 * sn));
}

// ---------------- tf32 tensor-core flash attention (fp16 output) ----------------
#define KPAD 68
#define VPAD 72
#define FA_SMEM ((2 * 64 * KPAD + 2 * 64 * VPAD + 64 * KPAD) * 4)

__global__ __launch_bounds__(128) void flash_mma(const float* __restrict__ Q,
                                                 const float* __restrict__ Kg,
                                                 const float* __restrict__ Vg,
                                                 const float* __restrict__ mask,
                                                 __half* __restrict__ O) {
    extern __shared__ unsigned sm[];
    unsigned (*Ks)[64][KPAD] = (unsigned(*)[64][KPAD])sm;
    unsigned (*Vs)[64][VPAD] = (unsigned(*)[64][VPAD])(sm + 2 * 64 * KPAD);
    unsigned (*Ps)[KPAD] = (unsigned(*)[KPAD])(sm + 2 * 64 * KPAD + 2 * 64 * VPAD);

    const int tid = threadIdx.x;
    const int warp = tid >> 5, lane = tid & 31;
    const int g = lane >> 2, tg = lane & 3;
    const int wm = warp * 16;

    const int h = blockIdx.y;
    const int kvh = h >> 2;
    const int qbase = blockIdx.x * 64;

    auto load_tiles = [&](int buf, int t) {
#pragma unroll
        for (int u = 0; u < 8; u++) {
            int slot = tid + u * 128;
            int r = slot >> 4, c4 = (slot & 15) * 4;
            cp_async16(&Ks[buf][r][c4], Kg + (size_t)(t + r) * (NKV * HD) + kvh * HD + c4);
            cp_async16(&Vs[buf][r][c4], Vg + (size_t)(t + r) * (NKV * HD) + kvh * HD + c4);
        }
    };

    unsigned qa[8][4];
    {
        const float* Qp = Q + (size_t)qbase * HID + h * HD;
        const int r0 = wm + g, r1 = wm + g + 8;
#pragma unroll
        for (int ks = 0; ks < 8; ks++) {
            qa[ks][0] = __float_as_uint(Qp[(size_t)r0 * HID + ks * 8 + tg] * 0.125f);
            qa[ks][1] = __float_as_uint(Qp[(size_t)r1 * HID + ks * 8 + tg] * 0.125f);
            qa[ks][2] = __float_as_uint(Qp[(size_t)r0 * HID + ks * 8 + tg + 4] * 0.125f);
            qa[ks][3] = __float_as_uint(Qp[(size_t)r1 * HID + ks * 8 + tg + 4] * 0.125f);
        }
    }

    float co[8][4] = {};
    float m_g = -1e30f, m_g8 = -1e30f, l_g = 0.f, l_g8 = 0.f;

    load_tiles(0, 0);
    cp_commit();

    for (int ti = 0; ti < S_LEN / 64; ti++) {
        const int t = ti * 64;
        if (ti + 1 < S_LEN / 64) load_tiles((ti + 1) & 1, t + 64);
        cp_commit();
        cp_wait<1>();
        __syncthreads();

        const int buf = ti & 1;

        float cs[8][4] = {};
#pragma unroll
        for (int ks = 0; ks < 8; ks++) {
#pragma unroll
            for (int nt = 0; nt < 8; nt++) {
                unsigned b[2];
                b[0] = Ks[buf][nt * 8 + g][ks * 8 + tg];
                b[1] = Ks[buf][nt * 8 + g][ks * 8 + tg + 4];
                mma_tf32(cs[nt], qa[ks], b);
            }
        }

        float mloc_g = -1e30f, mloc_g8 = -1e30f;
#pragma unroll
        for (int nt = 0; nt < 8; nt++) {
            float mk0 = __ldg(mask + t + nt * 8 + 2 * tg);
            float mk1 = __ldg(mask + t + nt * 8 + 2 * tg + 1);
            cs[nt][0] += mk0; cs[nt][1] += mk1;
            cs[nt][2] += mk0; cs[nt][3] += mk1;
            mloc_g  = fmaxf(mloc_g,  fmaxf(cs[nt][0], cs[nt][1]));
            mloc_g8 = fmaxf(mloc_g8, fmaxf(cs[nt][2], cs[nt][3]));
        }
        mloc_g  = fmaxf(mloc_g,  __shfl_xor_sync(0xffffffff, mloc_g, 1));
        mloc_g  = fmaxf(mloc_g,  __shfl_xor_sync(0xffffffff, mloc_g, 2));
        mloc_g8 = fmaxf(mloc_g8, __shfl_xor_sync(0xffffffff, mloc_g8, 1));
        mloc_g8 = fmaxf(mloc_g8, __shfl_xor_sync(0xffffffff, mloc_g8, 2));

        float mn_g  = fmaxf(m_g,  mloc_g);
        float mn_g8 = fmaxf(m_g8, mloc_g8);
        float corr_g  = __expf(m_g - mn_g);
        float corr_g8 = __expf(m_g8 - mn_g8);

        float sum_g = 0.f, sum_g8 = 0.f;
#pragma unroll
        for (int nt = 0; nt < 8; nt++) {
            float p0 = __expf(cs[nt][0] - mn_g);
            float p1 = __expf(cs[nt][1] - mn_g);
            float p2 = __expf(cs[nt][2] - mn_g8);
            float p3 = __expf(cs[nt][3] - mn_g8);
            sum_g += p0 + p1; sum_g8 += p2 + p3;
            Ps[wm + g][nt * 8 + 2 * tg]         = f2tf32(p0);
            Ps[wm + g][nt * 8 + 2 * tg + 1]     = f2tf32(p1);
            Ps[wm + g + 8][nt * 8 + 2 * tg]     = f2tf32(p2);
            Ps[wm + g + 8][nt * 8 + 2 * tg + 1] = f2tf32(p3);
            co[nt][0] *= corr_g;  co[nt][1] *= corr_g;
            co[nt][2] *= corr_g8; co[nt][3] *= corr_g8;
        }
        sum_g  += __shfl_xor_sync(0xffffffff, sum_g, 1);
        sum_g  += __shfl_xor_sync(0xffffffff, sum_g, 2);
        sum_g8 += __shfl_xor_sync(0xffffffff, sum_g8, 1);
        sum_g8 += __shfl_xor_sync(0xffffffff, sum_g8, 2);
        l_g  = l_g * corr_g + sum_g;
        l_g8 = l_g8 * corr_g8 + sum_g8;
        m_g = mn_g; m_g8 = mn_g8;
        __syncwarp();

#pragma unroll
        for (int ks = 0; ks < 8; ks++) {
            unsigned a[4];
            a[0] = Ps[wm + g][ks * 8 + tg];
            a[1] = Ps[wm + g + 8][ks * 8 + tg];
            a[2] = Ps[wm + g][ks * 8 + tg + 4];
            a[3] = Ps[wm + g + 8][ks * 8 + tg + 4];
#pragma unroll
            for (int nt = 0; nt < 8; nt++) {
                unsigned b[2];
                b[0] = Vs[buf][ks * 8 + tg][nt * 8 + g];
                b[1] = Vs[buf][ks * 8 + tg + 4][nt * 8 + g];
                mma_tf32(co[nt], a, b);
            }
        }
        __syncthreads();
    }

    const float inv_g  = 1.f / l_g;
    const float inv_g8 = 1.f / l_g8;
    const int row0 = qbase + wm + g;
#pragma unroll
    for (int nt = 0; nt < 8; nt++) {
        int col = h * HD + nt * 8 + 2 * tg;
        unsigned lo = pack_half2(co[nt][0] * inv_g, co[nt][1] * inv_g);
        unsigned hi = pack_half2(co[nt][2] * inv_g8, co[nt][3] * inv_g8);
        *(unsigned*)(O + (size_t)row0 * HID + col) = lo;
        *(unsigned*)(O + (size_t)(row0 + 8) * HID + col) = hi;
    }
}

// ---------------- host launcher ----------------
extern "C" void kernel_launch(void* const* d_in, const int* in_sizes, int n_in,
                              void* d_out, int out_size) {
    const float* x    = (const float*)d_in[0];
    const float* mask = (const float*)d_in[1];
    const int*   pos  = (const int*)d_in[2];
    const float* wq   = (const float*)d_in[3];
    const float* wk   = (const float*)d_in[4];
    const float* wv   = (const float*)d_in[5];
    const float* wo   = (const float*)d_in[6];
    float* out = (float*)d_out;

    float *pscale, *ppart, *pq, *pk, *pv;
    __half *pxh, *pwq, *pwk, *pwv, *pwo, *patth;
    cudaGetSymbolAddress((void**)&pscale, g_scale);
    cudaGetSymbolAddress((void**)&ppart,  g_part);
    cudaGetSymbolAddress((void**)&pxh,    g_xh);
    cudaGetSymbolAddress((void**)&pwq,    g_wq);
    cudaGetSymbolAddress((void**)&pwk,    g_wk);
    cudaGetSymbolAddress((void**)&pwv,    g_wv);
    cudaGetSymbolAddress((void**)&pwo,    g_wo);
    cudaGetSymbolAddress((void**)&pq,     g_q);
    cudaGetSymbolAddress((void**)&pk,     g_k);
    cudaGetSymbolAddress((void**)&pv,     g_v);
    cudaGetSymbolAddress((void**)&patth,  g_atth);

    cudaFuncSetAttribute(hgemm_pipe<true>,  cudaFuncAttributeMaxDynamicSharedMemorySize, HGEMM_SMEM);
    cudaFuncSetAttribute(hgemm_pipe<false>, cudaFuncAttributeMaxDynamicSharedMemorySize, HGEMM_SMEM);
    cudaFuncSetAttribute(flash_mma, cudaFuncAttributeMaxDynamicSharedMemorySize, FA_SMEM);

    // scales
    absmean_all_partial<<<dim3(256, 4), 256>>>(wq, wk, wv, wo, ppart);
    absmean_all_final<<<4, 256>>>(ppart, pscale);

    // pre-passes
    quantize_all_h<<<dim3(1024, 4), 256>>>(wq, wk, wv, wo, pwq, pwk, pwv, pwo, pscale);
    cvt_x_half<<<(S_LEN * HID / 4 + 255) / 256, 256>>>(x, pxh, S_LEN * HID / 4);

    // fp16 tensor-core projections
    hgemm_pipe<true><<<dim3(HID / GBN, S_LEN / GBM), 256, HGEMM_SMEM>>>(pxh, pwq, pq, HID, HID, pscale + 0);
    hgemm_pipe<true><<<dim3((NKV * HD) / GBN, S_LEN / GBM), 256, HGEMM_SMEM>>>(pxh, pwk, pk, NKV * HD, HID, pscale + 1);
    hgemm_pipe<true><<<dim3((NKV * HD) / GBN, S_LEN / GBM), 256, HGEMM_SMEM>>>(pxh, pwv, pv, NKV * HD, HID, pscale + 2);

    rope_kernel<<<(S_LEN * NH * 32 + 255) / 256, 256>>>(pq, pos, NH);
    rope_kernel<<<(S_LEN * NKV * 32 + 255) / 256, 256>>>(pk, pos, NKV);

    flash_mma<<<dim3(S_LEN / 64, NH), 128, FA_SMEM>>>(pq, pk, pv, mask, patth);

    hgemm_pipe<false><<<dim3(HID / GBN, S_LEN / GBM), 256, HGEMM_SMEM>>>(patth, pwo, out, HID, HID, pscale + 3);
}

// round 8
// speedup vs baseline: 6.2666x; 1.3339x over previous
#include <cuda_runtime.h>
#include <cuda_fp16.h>
#include <math.h>

#define S_LEN 2048
#define HID   2048
#define NH    32
#define NKV   8
#define HD    64

// ---------------- static scratch ----------------
static __device__ float  g_scale[4];
static __device__ float  g_part[4 * 256];
static __device__ __half g_xh[S_LEN * HID];          // fp16 activations
static __device__ __half g_wq[HID * HID];            // exact ternary fp16
static __device__ __half g_wk[NKV * HD * HID];
static __device__ __half g_wv[NKV * HD * HID];
static __device__ __half g_wo[HID * HID];
static __device__ __half g_qh[S_LEN * HID];          // Q fp16 (rope'd, pre-scaled 1/8)
static __device__ __half g_kh[S_LEN * NKV * HD];     // K fp16 (rope'd)
static __device__ __half g_vth[NKV * HD * S_LEN];    // V fp16 TRANSPOSED [d][seq]
static __device__ __half g_atth[S_LEN * HID];        // attention out (fp16)

// ---------------- helpers ----------------
__device__ __forceinline__ unsigned pack_half2(float lo, float hi) {
    __half2 h = __floats2half2_rn(lo, hi);
    return *(unsigned*)&h;
}

__device__ __forceinline__ void mma_f16(float c[4], const unsigned a[4], const unsigned b[2]) {
    asm volatile(
        "mma.sync.aligned.m16n8k16.row.col.f32.f16.f16.f32 "
        "{%0,%1,%2,%3}, {%4,%5,%6,%7}, {%8,%9}, {%0,%1,%2,%3};"
        : "+f"(c[0]), "+f"(c[1]), "+f"(c[2]), "+f"(c[3])
        : "r"(a[0]), "r"(a[1]), "r"(a[2]), "r"(a[3]), "r"(b[0]), "r"(b[1]));
}

__device__ __forceinline__ void cp_async16(void* smem_dst, const void* gptr) {
    unsigned s = (unsigned)__cvta_generic_to_shared(smem_dst);
    asm volatile("cp.async.cg.shared.global [%0], [%1], 16;" :: "r"(s), "l"(gptr));
}
__device__ __forceinline__ void cp_commit() { asm volatile("cp.async.commit_group;"); }
template <int N>
__device__ __forceinline__ void cp_wait() { asm volatile("cp.async.wait_group %0;" :: "n"(N)); }

// ---------------- fused absmean (deterministic two-stage) ----------------
__global__ void absmean_all_partial(const float* __restrict__ wq, const float* __restrict__ wk,
                                    const float* __restrict__ wv, const float* __restrict__ wo,
                                    float* __restrict__ part) {
    __shared__ float red[256];
    int t = blockIdx.y;
    const float* w = t == 0 ? wq : t == 1 ? wk : t == 2 ? wv : wo;
    int n = (t == 0 || t == 3) ? HID * HID : NKV * HD * HID;
    float s = 0.f;
    for (int i = blockIdx.x * blockDim.x + threadIdx.x; i < n; i += gridDim.x * blockDim.x)
        s += fabsf(w[i]);
    red[threadIdx.x] = s;
    __syncthreads();
    for (int o = 128; o > 0; o >>= 1) {
        if (threadIdx.x < o) red[threadIdx.x] += red[threadIdx.x + o];
        __syncthreads();
    }
    if (threadIdx.x == 0) part[t * 256 + blockIdx.x] = red[0];
}

__global__ void absmean_all_final(const float* __restrict__ part, float* __restrict__ scale) {
    __shared__ float red[256];
    int t = blockIdx.x;
    int n = (t == 0 || t == 3) ? HID * HID : NKV * HD * HID;
    red[threadIdx.x] = part[t * 256 + threadIdx.x];
    __syncthreads();
    for (int o = 128; o > 0; o >>= 1) {
        if (threadIdx.x < o) red[threadIdx.x] += red[threadIdx.x + o];
        __syncthreads();
    }
    if (threadIdx.x == 0) scale[t] = red[0] / (float)n + 1e-6f;
}

// ---------------- ternary quantization -> exact fp16 {-1,0,1} ----------------
__global__ void quantize_all_h(const float* __restrict__ wq, const float* __restrict__ wk,
                               const float* __restrict__ wv, const float* __restrict__ wo,
                               __half* __restrict__ oq, __half* __restrict__ ok,
                               __half* __restrict__ ov, __half* __restrict__ oo,
                               const float* __restrict__ scales) {
    int t = blockIdx.y;
    const float4* w = (const float4*)(t == 0 ? wq : t == 1 ? wk : t == 2 ? wv : wo);
    __half* o = (t == 0 ? oq : t == 1 ? ok : t == 2 ? ov : oo);
    int n4 = ((t == 0 || t == 3) ? HID * HID : NKV * HD * HID) >> 2;
    float inv = 1.f / scales[t];
    for (int i = blockIdx.x * blockDim.x + threadIdx.x; i < n4; i += gridDim.x * blockDim.x) {
        float4 v = w[i];
        unsigned u0 = pack_half2(rintf(fminf(fmaxf(v.x * inv, -1.f), 1.f)),
                                 rintf(fminf(fmaxf(v.y * inv, -1.f), 1.f)));
        unsigned u1 = pack_half2(rintf(fminf(fmaxf(v.z * inv, -1.f), 1.f)),
                                 rintf(fminf(fmaxf(v.w * inv, -1.f), 1.f)));
        ((uint2*)o)[i] = make_uint2(u0, u1);
    }
}

// ---------------- fp32 -> fp16 activations ----------------
__global__ void cvt_x_half(const float* __restrict__ in, __half* __restrict__ out, int n4) {
    int i = blockIdx.x * blockDim.x + threadIdx.x;
    if (i >= n4) return;
    float4 v = ((const float4*)in)[i];
    ((uint2*)out)[i] = make_uint2(pack_half2(v.x, v.y), pack_half2(v.z, v.w));
}

// ---------------- fp16 tensor-core GEMM ----------------
// MODE 0: C fp32 [M][N];  MODE 1: C fp16 [M][N];  MODE 2: C fp16 transposed [N][M].
#define GBM 128
#define GBN 128
#define GBKH 32
#define PADH 40
#define STAGES 3
#define HGEMM_SMEM (STAGES * 2 * GBM * PADH * 2)

template <int MODE>
__global__ __launch_bounds__(256) void hgemm_pipe(const __half* __restrict__ A,
                                                  const __half* __restrict__ W,
                                                  void* __restrict__ Cv,
                                                  int N, int K,
                                                  const float* __restrict__ scale_p) {
    extern __shared__ __half hsm[];
    __half* Ah = hsm;
    __half* Bh = hsm + STAGES * GBM * PADH;

    const int tid = threadIdx.x;
    const float scale = *scale_p;
    const int bm = blockIdx.y * GBM;
    const int bn = blockIdx.x * GBN;

    const int warp = tid >> 5, lane = tid & 31;
    const int wm = (warp & 1) * 64;
    const int wn = (warp >> 1) * 32;
    const int g = lane >> 2, tg = lane & 3;

    const __half* Ap = A + (size_t)bm * K;
    const __half* Wp = W + (size_t)bn * K;

    float c[4][4][4] = {};
    const int ntiles = K / GBKH;

    auto load_tile = [&](int stage, int k0) {
#pragma unroll
        for (int i = 0; i < 2; i++) {
            int ch = tid + i * 256;
            int r = ch >> 2, c8 = (ch & 3) * 8;
            cp_async16(Ah + stage * GBM * PADH + r * PADH + c8, Ap + (size_t)r * K + k0 + c8);
            cp_async16(Bh + stage * GBM * PADH + r * PADH + c8, Wp + (size_t)r * K + k0 + c8);
        }
    };

#pragma unroll
    for (int s = 0; s < STAGES - 1; s++) {
        load_tile(s, s * GBKH);
        cp_commit();
    }

    for (int kt = 0; kt < ntiles; kt++) {
        cp_wait<STAGES - 2>();
        __syncthreads();

        int kn = kt + STAGES - 1;
        if (kn < ntiles) load_tile(kn % STAGES, kn * GBKH);
        cp_commit();

        const __half* As = Ah + (kt % STAGES) * GBM * PADH;
        const __half* Bs = Bh + (kt % STAGES) * GBM * PADH;

#pragma unroll
        for (int ks = 0; ks < GBKH; ks += 16) {
            unsigned a[4][4], b[4][2];
#pragma unroll
            for (int mt = 0; mt < 4; mt++) {
                int r = wm + mt * 16 + g;
                a[mt][0] = *(const unsigned*)(As + r * PADH + ks + 2 * tg);
                a[mt][1] = *(const unsigned*)(As + (r + 8) * PADH + ks + 2 * tg);
                a[mt][2] = *(const unsigned*)(As + r * PADH + ks + 2 * tg + 8);
                a[mt][3] = *(const unsigned*)(As + (r + 8) * PADH + ks + 2 * tg + 8);
            }
#pragma unroll
            for (int nt = 0; nt < 4; nt++) {
                int nr = wn + nt * 8 + g;
                b[nt][0] = *(const unsigned*)(Bs + nr * PADH + ks + 2 * tg);
                b[nt][1] = *(const unsigned*)(Bs + nr * PADH + ks + 2 * tg + 8);
            }
#pragma unroll
            for (int mt = 0; mt < 4; mt++)
#pragma unroll
                for (int nt = 0; nt < 4; nt++)
                    mma_f16(c[mt][nt], a[mt], b[nt]);
        }
        __syncthreads();
    }

#pragma unroll
    for (int mt = 0; mt < 4; mt++) {
#pragma unroll
        for (int nt = 0; nt < 4; nt++) {
            int row = bm + wm + mt * 16 + g;
            int col = bn + wn + nt * 8 + 2 * tg;
            float v0 = c[mt][nt][0] * scale, v1 = c[mt][nt][1] * scale;
            float v2 = c[mt][nt][2] * scale, v3 = c[mt][nt][3] * scale;
            if (MODE == 0) {
                float* C = (float*)Cv;
                *(float2*)(C + (size_t)row * N + col) = make_float2(v0, v1);
                *(float2*)(C + (size_t)(row + 8) * N + col) = make_float2(v2, v3);
            } else if (MODE == 1) {
                __half* C = (__half*)Cv;
                *(unsigned*)(C + (size_t)row * N + col) = pack_half2(v0, v1);
                *(unsigned*)(C + (size_t)(row + 8) * N + col) = pack_half2(v2, v3);
            } else {
                __half* C = (__half*)Cv;   // [N][S_LEN]
                C[(size_t)col * S_LEN + row]           = __float2half_rn(v0);
                C[(size_t)(col + 1) * S_LEN + row]     = __float2half_rn(v1);
                C[(size_t)col * S_LEN + row + 8]       = __float2half_rn(v2);
                C[(size_t)(col + 1) * S_LEN + row + 8] = __float2half_rn(v3);
            }
        }
    }
}

// ---------------- RoPE on fp16 (in place), x layout [S, nheads, 64] ----------------
__global__ void rope_h(__half* __restrict__ x, const int* __restrict__ pos_ids,
                       int nheads, float s_mul) {
    int idx = blockIdx.x * blockDim.x + threadIdx.x;
    int total = S_LEN * nheads * 32;
    if (idx >= total) return;
    int i = idx & 31;
    int h = (idx >> 5) % nheads;
    int s = idx / (32 * nheads);
    float pos = (float)pos_ids[s];
    float inv_freq = powf(10000.f, -(float)(2 * i) / 64.f);
    float ang = pos * inv_freq;
    float c = cosf(ang), sn = sinf(ang);
    __half* base = x + ((size_t)s * nheads + h) * HD;
    float x1 = __half2float(base[i]), x2 = __half2float(base[i + 32]);
    base[i]      = __float2half_rn(s_mul * (x1 * c - x2 * sn));
    base[i + 32] = __float2half_rn(s_mul * (x2 * c + x1 * sn));
}

// ---------------- fp16 tensor-core flash attention ----------------
// K tile [key][d] pad 72 halves; V tile pre-transposed [d][key] pad 72.
// P stays in registers (S C-frag layout == PV A-frag layout).
#define KPADH 72
#define FAH_SMEM (4 * 64 * KPADH * 2)

__global__ __launch_bounds__(128) void flash_h(const __half* __restrict__ Qh,
                                               const __half* __restrict__ Kg,
                                               const __half* __restrict__ Vtg,
                                               const float* __restrict__ mask,
                                               __half* __restrict__ O) {
    extern __shared__ __half hs[];
    __half (*Ks)[64][KPADH] = (__half(*)[64][KPADH])hs;
    __half (*Vs)[64][KPADH] = (__half(*)[64][KPADH])(hs + 2 * 64 * KPADH);

    const int tid = threadIdx.x;
    const int warp = tid >> 5, lane = tid & 31;
    const int g = lane >> 2, tg = lane & 3;
    const int wm = warp * 16;

    const int h = blockIdx.y;
    const int kvh = h >> 2;
    const int qbase = blockIdx.x * 64;

    auto load_tiles = [&](int buf, int t) {
#pragma unroll
        for (int u = 0; u < 4; u++) {
            int slot = tid + u * 128;            // 0..511
            int r = slot >> 3, c8 = (slot & 7) * 8;
            cp_async16(&Ks[buf][r][c8], Kg + (size_t)(t + r) * (NKV * HD) + kvh * HD + c8);
            cp_async16(&Vs[buf][r][c8], Vtg + (size_t)(kvh * HD + r) * S_LEN + t + c8);
        }
    };

    // Q fragments (fp16, pre-scaled by 1/8 in rope)
    unsigned qa[4][4];
    {
        const __half* Qp = Qh + (size_t)qbase * HID + h * HD;
        const int r0 = wm + g, r1 = wm + g + 8;
#pragma unroll
        for (int ks = 0; ks < 4; ks++) {
            qa[ks][0] = *(const unsigned*)(Qp + (size_t)r0 * HID + ks * 16 + 2 * tg);
            qa[ks][1] = *(const unsigned*)(Qp + (size_t)r1 * HID + ks * 16 + 2 * tg);
            qa[ks][2] = *(const unsigned*)(Qp + (size_t)r0 * HID + ks * 16 + 2 * tg + 8);
            qa[ks][3] = *(const unsigned*)(Qp + (size_t)r1 * HID + ks * 16 + 2 * tg + 8);
        }
    }

    float co[8][4] = {};
    float m_g = -1e30f, m_g8 = -1e30f, l_g = 0.f, l_g8 = 0.f;

    load_tiles(0, 0);
    cp_commit();

    for (int ti = 0; ti < S_LEN / 64; ti++) {
        const int t = ti * 64;
        if (ti + 1 < S_LEN / 64) load_tiles((ti + 1) & 1, t + 64);
        cp_commit();
        cp_wait<1>();
        __syncthreads();

        const int buf = ti & 1;

        // S = Q K^T  (fp16, 4 k-steps)
        float cs[8][4] = {};
#pragma unroll
        for (int ks = 0; ks < 4; ks++) {
#pragma unroll
            for (int nt = 0; nt < 8; nt++) {
                unsigned b[2];
                b[0] = *(const unsigned*)&Ks[buf][nt * 8 + g][ks * 16 + 2 * tg];
                b[1] = *(const unsigned*)&Ks[buf][nt * 8 + g][ks * 16 + 2 * tg + 8];
                mma_f16(cs[nt], qa[ks], b);
            }
        }

        // mask + row max
        float mloc_g = -1e30f, mloc_g8 = -1e30f;
#pragma unroll
        for (int nt = 0; nt < 8; nt++) {
            float mk0 = __ldg(mask + t + nt * 8 + 2 * tg);
            float mk1 = __ldg(mask + t + nt * 8 + 2 * tg + 1);
            cs[nt][0] += mk0; cs[nt][1] += mk1;
            cs[nt][2] += mk0; cs[nt][3] += mk1;
            mloc_g  = fmaxf(mloc_g,  fmaxf(cs[nt][0], cs[nt][1]));
            mloc_g8 = fmaxf(mloc_g8, fmaxf(cs[nt][2], cs[nt][3]));
        }
        mloc_g  = fmaxf(mloc_g,  __shfl_xor_sync(0xffffffff, mloc_g, 1));
        mloc_g  = fmaxf(mloc_g,  __shfl_xor_sync(0xffffffff, mloc_g, 2));
        mloc_g8 = fmaxf(mloc_g8, __shfl_xor_sync(0xffffffff, mloc_g8, 1));
        mloc_g8 = fmaxf(mloc_g8, __shfl_xor_sync(0xffffffff, mloc_g8, 2));

        float mn_g  = fmaxf(m_g,  mloc_g);
        float mn_g8 = fmaxf(m_g8, mloc_g8);
        float corr_g  = __expf(m_g - mn_g);
        float corr_g8 = __expf(m_g8 - mn_g8);

        // exp in place; accumulate row sums
        float sum_g = 0.f, sum_g8 = 0.f;
#pragma unroll
        for (int nt = 0; nt < 8; nt++) {
            cs[nt][0] = __expf(cs[nt][0] - mn_g);
            cs[nt][1] = __expf(cs[nt][1] - mn_g);
            cs[nt][2] = __expf(cs[nt][2] - mn_g8);
            cs[nt][3] = __expf(cs[nt][3] - mn_g8);
            sum_g  += cs[nt][0] + cs[nt][1];
            sum_g8 += cs[nt][2] + cs[nt][3];
            co[nt][0] *= corr_g;  co[nt][1] *= corr_g;
            co[nt][2] *= corr_g8; co[nt][3] *= corr_g8;
        }
        sum_g  += __shfl_xor_sync(0xffffffff, sum_g, 1);
        sum_g  += __shfl_xor_sync(0xffffffff, sum_g, 2);
        sum_g8 += __shfl_xor_sync(0xffffffff, sum_g8, 1);
        sum_g8 += __shfl_xor_sync(0xffffffff, sum_g8, 2);
        l_g  = l_g * corr_g + sum_g;
        l_g8 = l_g8 * corr_g8 + sum_g8;
        m_g = mn_g; m_g8 = mn_g8;

        // O += P V  — P packed from C-fragments directly (no smem)
#pragma unroll
        for (int kk = 0; kk < 4; kk++) {
            unsigned a[4];
            a[0] = pack_half2(cs[2 * kk][0],     cs[2 * kk][1]);
            a[1] = pack_half2(cs[2 * kk][2],     cs[2 * kk][3]);
            a[2] = pack_half2(cs[2 * kk + 1][0], cs[2 * kk + 1][1]);
            a[3] = pack_half2(cs[2 * kk + 1][2], cs[2 * kk + 1][3]);
#pragma unroll
            for (int nt = 0; nt < 8; nt++) {
                unsigned b[2];
                b[0] = *(const unsigned*)&Vs[buf][nt * 8 + g][kk * 16 + 2 * tg];
                b[1] = *(const unsigned*)&Vs[buf][nt * 8 + g][kk * 16 + 2 * tg + 8];
                mma_f16(co[nt], a, b);
            }
        }
        __syncthreads();
    }

    const float inv_g  = 1.f / l_g;
    const float inv_g8 = 1.f / l_g8;
    const int row0 = qbase + wm + g;
#pragma unroll
    for (int nt = 0; nt < 8; nt++) {
        int col = h * HD + nt * 8 + 2 * tg;
        *(unsigned*)(O + (size_t)row0 * HID + col) =
            pack_half2(co[nt][0] * inv_g, co[nt][1] * inv_g);
        *(unsigned*)(O + (size_t)(row0 + 8) * HID + col) =
            pack_half2(co[nt][2] * inv_g8, co[nt][3] * inv_g8);
    }
}

// ---------------- host launcher ----------------
extern "C" void kernel_launch(void* const* d_in, const int* in_sizes, int n_in,
                              void* d_out, int out_size) {
    const float* x    = (const float*)d_in[0];
    const float* mask = (const float*)d_in[1];
    const int*   pos  = (const int*)d_in[2];
    const float* wq   = (const float*)d_in[3];
    const float* wk   = (const float*)d_in[4];
    const float* wv   = (const float*)d_in[5];
    const float* wo   = (const float*)d_in[6];
    float* out = (float*)d_out;

    float *pscale, *ppart;
    __half *pxh, *pwq, *pwk, *pwv, *pwo, *pqh, *pkh, *pvth, *patth;
    cudaGetSymbolAddress((void**)&pscale, g_scale);
    cudaGetSymbolAddress((void**)&ppart,  g_part);
    cudaGetSymbolAddress((void**)&pxh,    g_xh);
    cudaGetSymbolAddress((void**)&pwq,    g_wq);
    cudaGetSymbolAddress((void**)&pwk,    g_wk);
    cudaGetSymbolAddress((void**)&pwv,    g_wv);
    cudaGetSymbolAddress((void**)&pwo,    g_wo);
    cudaGetSymbolAddress((void**)&pqh,    g_qh);
    cudaGetSymbolAddress((void**)&pkh,    g_kh);
    cudaGetSymbolAddress((void**)&pvth,   g_vth);
    cudaGetSymbolAddress((void**)&patth,  g_atth);

    cudaFuncSetAttribute(hgemm_pipe<0>, cudaFuncAttributeMaxDynamicSharedMemorySize, HGEMM_SMEM);
    cudaFuncSetAttribute(hgemm_pipe<1>, cudaFuncAttributeMaxDynamicSharedMemorySize, HGEMM_SMEM);
    cudaFuncSetAttribute(hgemm_pipe<2>, cudaFuncAttributeMaxDynamicSharedMemorySize, HGEMM_SMEM);
    cudaFuncSetAttribute(flash_h, cudaFuncAttributeMaxDynamicSharedMemorySize, FAH_SMEM);

    // scales
    absmean_all_partial<<<dim3(256, 4), 256>>>(wq, wk, wv, wo, ppart);
    absmean_all_final<<<4, 256>>>(ppart, pscale);

    // pre-passes
    quantize_all_h<<<dim3(1024, 4), 256>>>(wq, wk, wv, wo, pwq, pwk, pwv, pwo, pscale);
    cvt_x_half<<<(S_LEN * HID / 4 + 255) / 256, 256>>>(x, pxh, S_LEN * HID / 4);

    // fp16 tensor-core projections
    hgemm_pipe<1><<<dim3(HID / GBN, S_LEN / GBM), 256, HGEMM_SMEM>>>(pxh, pwq, pqh, HID, HID, pscale + 0);
    hgemm_pipe<1><<<dim3((NKV * HD) / GBN, S_LEN / GBM), 256, HGEMM_SMEM>>>(pxh, pwk, pkh, NKV * HD, HID, pscale + 1);
    hgemm_pipe<2><<<dim3((NKV * HD) / GBN, S_LEN / GBM), 256, HGEMM_SMEM>>>(pxh, pwv, pvth, NKV * HD, HID, pscale + 2);

    // RoPE (Q pre-scaled by 1/sqrt(64))
    rope_h<<<(S_LEN * NH * 32 + 255) / 256, 256>>>(pqh, pos, NH, 0.125f);
    rope_h<<<(S_LEN * NKV * 32 + 255) / 256, 256>>>(pkh, pos, NKV, 1.0f);

    // fp16 flash attention
    flash_h<<<dim3(S_LEN / 64, NH), 128, FAH_SMEM>>>(pqh, pkh, pvth, mask, patth);

    // output projection (fp32 out)
    hgemm_pipe<0><<<dim3(HID / GBN, S_LEN / GBM), 256, HGEMM_SMEM>>>(patth, pwo, out, HID, HID, pscale + 3);
}

// round 9
// speedup vs baseline: 6.4937x; 1.0362x over previous
#include <cuda_runtime.h>
#include <cuda_fp16.h>
#include <math.h>

#define S_LEN 2048
#define HID   2048
#define NH    32
#define NKV   8
#define HD    64

// ---------------- static scratch ----------------
static __device__ float  g_scale[4];
static __device__ float  g_part[4 * 256];
static __device__ __half g_xh[S_LEN * HID];            // fp16 activations
static __device__ __half g_wqkv[3072 * HID];           // concat ternary: Q[0:2048) K[2048:2560) V[2560:3072)
static __device__ __half g_wo[HID * HID];
static __device__ __half g_qh[S_LEN * HID];            // Q (rope'd, pre-scaled 1/8)
static __device__ __half g_kh[S_LEN * NKV * HD];       // K (rope'd)
static __device__ __half g_vth[NKV * HD * S_LEN];      // V TRANSPOSED [d][seq]
static __device__ __half g_atth[S_LEN * HID];          // attention out

// ---------------- helpers ----------------
__device__ __forceinline__ unsigned pack_half2(float lo, float hi) {
    __half2 h = __floats2half2_rn(lo, hi);
    return *(unsigned*)&h;
}

__device__ __forceinline__ void mma_f16(float c[4], const unsigned a[4], const unsigned b[2]) {
    asm volatile(
        "mma.sync.aligned.m16n8k16.row.col.f32.f16.f16.f32 "
        "{%0,%1,%2,%3}, {%4,%5,%6,%7}, {%8,%9}, {%0,%1,%2,%3};"
        : "+f"(c[0]), "+f"(c[1]), "+f"(c[2]), "+f"(c[3])
        : "r"(a[0]), "r"(a[1]), "r"(a[2]), "r"(a[3]), "r"(b[0]), "r"(b[1]));
}

__device__ __forceinline__ void ldsm4(unsigned r[4], const __half* p) {
    unsigned addr = (unsigned)__cvta_generic_to_shared(p);
    asm volatile("ldmatrix.sync.aligned.m8n8.x4.shared.b16 {%0,%1,%2,%3}, [%4];"
                 : "=r"(r[0]), "=r"(r[1]), "=r"(r[2]), "=r"(r[3]) : "r"(addr));
}

__device__ __forceinline__ void cp_async16(void* smem_dst, const void* gptr) {
    unsigned s = (unsigned)__cvta_generic_to_shared(smem_dst);
    asm volatile("cp.async.cg.shared.global [%0], [%1], 16;" :: "r"(s), "l"(gptr));
}
__device__ __forceinline__ void cp_commit() { asm volatile("cp.async.commit_group;"); }
template <int N>
__device__ __forceinline__ void cp_wait() { asm volatile("cp.async.wait_group %0;" :: "n"(N)); }

// ---------------- fused absmean (deterministic two-stage) ----------------
__global__ void absmean_all_partial(const float* __restrict__ wq, const float* __restrict__ wk,
                                    const float* __restrict__ wv, const float* __restrict__ wo,
                                    float* __restrict__ part) {
    __shared__ float red[256];
    int t = blockIdx.y;
    const float* w = t == 0 ? wq : t == 1 ? wk : t == 2 ? wv : wo;
    int n = (t == 0 || t == 3) ? HID * HID : NKV * HD * HID;
    float s0 = 0.f, s1 = 0.f, s2 = 0.f, s3 = 0.f;
    int stride = gridDim.x * blockDim.x;
    for (int i = blockIdx.x * blockDim.x + threadIdx.x; i < n; i += 4 * stride) {
        s0 += fabsf(w[i]);
        if (i + stride < n)     s1 += fabsf(w[i + stride]);
        if (i + 2 * stride < n) s2 += fabsf(w[i + 2 * stride]);
        if (i + 3 * stride < n) s3 += fabsf(w[i + 3 * stride]);
    }
    red[threadIdx.x] = (s0 + s1) + (s2 + s3);
    __syncthreads();
    for (int o = 128; o > 0; o >>= 1) {
        if (threadIdx.x < o) red[threadIdx.x] += red[threadIdx.x + o];
        __syncthreads();
    }
    if (threadIdx.x == 0) part[t * 256 + blockIdx.x] = red[0];
}

__global__ void absmean_all_final(const float* __restrict__ part, float* __restrict__ scale) {
    __shared__ float red[256];
    int t = blockIdx.x;
    int n = (t == 0 || t == 3) ? HID * HID : NKV * HD * HID;
    red[threadIdx.x] = part[t * 256 + threadIdx.x];
    __syncthreads();
    for (int o = 128; o > 0; o >>= 1) {
        if (threadIdx.x < o) red[threadIdx.x] += red[threadIdx.x + o];
        __syncthreads();
    }
    if (threadIdx.x == 0) scale[t] = red[0] / (float)n + 1e-6f;
}

// ---------------- ternary quantization -> exact fp16, MLP-4 ----------------
__global__ void quantize_all_h(const float* __restrict__ wq, const float* __restrict__ wk,
                               const float* __restrict__ wv, const float* __restrict__ wo,
                               __half* __restrict__ oqkv, __half* __restrict__ oo,
                               const float* __restrict__ scales) {
    int t = blockIdx.y;
    const float4* w = (const float4*)(t == 0 ? wq : t == 1 ? wk : t == 2 ? wv : wo);
    __half* o = t == 0 ? oqkv : t == 1 ? oqkv + 2048 * HID
                        : t == 2 ? oqkv + 2560 * HID : oo;
    int n4 = ((t == 0 || t == 3) ? HID * HID : NKV * HD * HID) >> 2;
    float inv = 1.f / scales[t];
    int stride = gridDim.x * blockDim.x;
    for (int i0 = blockIdx.x * blockDim.x + threadIdx.x; i0 < n4; i0 += 4 * stride) {
        float4 v[4];
        int cnt = 0;
#pragma unroll
        for (int j = 0; j < 4; j++) {
            int idx = i0 + j * stride;
            if (idx < n4) { v[j] = w[idx]; cnt = j + 1; }
        }
#pragma unroll
        for (int j = 0; j < 4; j++) {
            int idx = i0 + j * stride;
            if (j < cnt && idx < n4) {
                unsigned u0 = pack_half2(rintf(fminf(fmaxf(v[j].x * inv, -1.f), 1.f)),
                                         rintf(fminf(fmaxf(v[j].y * inv, -1.f), 1.f)));
                unsigned u1 = pack_half2(rintf(fminf(fmaxf(v[j].z * inv, -1.f), 1.f)),
                                         rintf(fminf(fmaxf(v[j].w * inv, -1.f), 1.f)));
                ((uint2*)o)[idx] = make_uint2(u0, u1);
            }
        }
    }
}

// ---------------- fp32 -> fp16 activations, MLP-4 ----------------
__global__ void cvt_x_half(const float* __restrict__ in, __half* __restrict__ out, int n4) {
    int i0 = blockIdx.x * blockDim.x * 4 + threadIdx.x;
    float4 v[4];
#pragma unroll
    for (int j = 0; j < 4; j++) {
        int idx = i0 + j * blockDim.x;
        if (idx < n4) v[j] = ((const float4*)in)[idx];
    }
#pragma unroll
    for (int j = 0; j < 4; j++) {
        int idx = i0 + j * blockDim.x;
        if (idx < n4)
            ((uint2*)out)[idx] = make_uint2(pack_half2(v[j].x, v[j].y), pack_half2(v[j].z, v[j].w));
    }
}

// ---------------- GEMM common ----------------
#define GBM 128
#define GBN 128
#define GBKH 32
#define PADH 40
#define STAGES 3
#define HGEMM_SMEM (STAGES * 2 * GBM * PADH * 2)

// mainloop macro body shared by the two GEMM kernels via inline function
struct Frag { float c[4][4][4]; };

__device__ __forceinline__ void hgemm_mainloop(const __half* __restrict__ Ap,
                                               const __half* __restrict__ Wp,
                                               __half* Ah, __half* Bh,
                                               int K, int tid, int wm, int wn,
                                               int lane, Frag& F) {
    const int a_row = lane & 15;
    const int a_col = (lane >> 4) * 8;
    const int b_sel = lane >> 4;            // 0/1: which nt of the pair
    const int b_row = lane & 7;
    const int b_col = ((lane >> 3) & 1) * 8;

    const int ntiles = K / GBKH;

    auto load_tile = [&](int stage, int k0) {
#pragma unroll
        for (int i = 0; i < 2; i++) {
            int ch = tid + i * 256;
            int r = ch >> 2, c8 = (ch & 3) * 8;
            cp_async16(Ah + stage * GBM * PADH + r * PADH + c8, Ap + (size_t)r * K + k0 + c8);
            cp_async16(Bh + stage * GBM * PADH + r * PADH + c8, Wp + (size_t)r * K + k0 + c8);
        }
    };

#pragma unroll
    for (int s = 0; s < STAGES - 1; s++) {
        load_tile(s, s * GBKH);
        cp_commit();
    }

    for (int kt = 0; kt < ntiles; kt++) {
        cp_wait<STAGES - 2>();
        __syncthreads();

        int kn = kt + STAGES - 1;
        if (kn < ntiles) load_tile(kn % STAGES, kn * GBKH);
        cp_commit();

        const __half* As = Ah + (kt % STAGES) * GBM * PADH;
        const __half* Bs = Bh + (kt % STAGES) * GBM * PADH;

#pragma unroll
        for (int ks = 0; ks < GBKH; ks += 16) {
            unsigned a[4][4], b[4][2];
#pragma unroll
            for (int mt = 0; mt < 4; mt++)
                ldsm4(a[mt], As + (wm + mt * 16 + a_row) * PADH + ks + a_col);
#pragma unroll
            for (int j = 0; j < 2; j++) {
                unsigned bb[4];
                ldsm4(bb, Bs + (wn + (2 * j + b_sel) * 8 + b_row) * PADH + ks + b_col);
                b[2 * j][0] = bb[0]; b[2 * j][1] = bb[1];
                b[2 * j + 1][0] = bb[2]; b[2 * j + 1][1] = bb[3];
            }
#pragma unroll
            for (int mt = 0; mt < 4; mt++)
#pragma unroll
                for (int nt = 0; nt < 4; nt++)
                    mma_f16(F.c[mt][nt], a[mt], b[nt]);
        }
        __syncthreads();
    }
}

// ---------------- fused QKV GEMM ----------------
// grid (24, 16): bx<16 -> Q [S][2048] fp16; bx 16..19 -> K [S][512] fp16;
// bx 20..23 -> V transposed [512][S] fp16.
__global__ __launch_bounds__(256) void hgemm_qkv(const __half* __restrict__ A,
                                                 const __half* __restrict__ Wqkv,
                                                 __half* __restrict__ Qout,
                                                 __half* __restrict__ Kout,
                                                 __half* __restrict__ Vtout,
                                                 const float* __restrict__ scales) {
    extern __shared__ __half hsm[];
    __half* Ah = hsm;
    __half* Bh = hsm + STAGES * GBM * PADH;

    const int tid = threadIdx.x;
    const int bx = blockIdx.x;
    const int bm = blockIdx.y * GBM;
    const int bn = bx * GBN;
    const int warp = tid >> 5, lane = tid & 31;
    const int wm = (warp & 1) * 64;
    const int wn = (warp >> 1) * 32;
    const int g = lane >> 2, tg = lane & 3;

    Frag F = {};
    hgemm_mainloop(A + (size_t)bm * HID, Wqkv + (size_t)bn * HID, Ah, Bh,
                   HID, tid, wm, wn, lane, F);

    const int region = bx < 16 ? 0 : (bx < 20 ? 1 : 2);
    const float scale = scales[region];

#pragma unroll
    for (int mt = 0; mt < 4; mt++) {
#pragma unroll
        for (int nt = 0; nt < 4; nt++) {
            int row = bm + wm + mt * 16 + g;
            int cb = wn + nt * 8 + 2 * tg;
            float v0 = F.c[mt][nt][0] * scale, v1 = F.c[mt][nt][1] * scale;
            float v2 = F.c[mt][nt][2] * scale, v3 = F.c[mt][nt][3] * scale;
            if (region == 0) {
                int col = bn + cb;
                *(unsigned*)(Qout + (size_t)row * HID + col) = pack_half2(v0, v1);
                *(unsigned*)(Qout + (size_t)(row + 8) * HID + col) = pack_half2(v2, v3);
            } else if (region == 1) {
                int col = bn - 2048 + cb;
                *(unsigned*)(Kout + (size_t)row * (NKV * HD) + col) = pack_half2(v0, v1);
                *(unsigned*)(Kout + (size_t)(row + 8) * (NKV * HD) + col) = pack_half2(v2, v3);
            } else {
                int col = bn - 2560 + cb;
                Vtout[(size_t)col * S_LEN + row]           = __float2half_rn(v0);
                Vtout[(size_t)(col + 1) * S_LEN + row]     = __float2half_rn(v1);
                Vtout[(size_t)col * S_LEN + row + 8]       = __float2half_rn(v2);
                Vtout[(size_t)(col + 1) * S_LEN + row + 8] = __float2half_rn(v3);
            }
        }
    }
}

// ---------------- output GEMM (fp32 out) ----------------
__global__ __launch_bounds__(256) void hgemm_out(const __half* __restrict__ A,
                                                 const __half* __restrict__ W,
                                                 float* __restrict__ C,
                                                 const float* __restrict__ scale_p) {
    extern __shared__ __half hsm[];
    __half* Ah = hsm;
    __half* Bh = hsm + STAGES * GBM * PADH;

    const int tid = threadIdx.x;
    const float scale = *scale_p;
    const int bm = blockIdx.y * GBM;
    const int bn = blockIdx.x * GBN;
    const int warp = tid >> 5, lane = tid & 31;
    const int wm = (warp & 1) * 64;
    const int wn = (warp >> 1) * 32;
    const int g = lane >> 2, tg = lane & 3;

    Frag F = {};
    hgemm_mainloop(A + (size_t)bm * HID, W + (size_t)bn * HID, Ah, Bh,
                   HID, tid, wm, wn, lane, F);

#pragma unroll
    for (int mt = 0; mt < 4; mt++) {
#pragma unroll
        for (int nt = 0; nt < 4; nt++) {
            int row = bm + wm + mt * 16 + g;
            int col = bn + wn + nt * 8 + 2 * tg;
            *(float2*)(C + (size_t)row * HID + col) =
                make_float2(F.c[mt][nt][0] * scale, F.c[mt][nt][1] * scale);
            *(float2*)(C + (size_t)(row + 8) * HID + col) =
                make_float2(F.c[mt][nt][2] * scale, F.c[mt][nt][3] * scale);
        }
    }
}

// ---------------- RoPE on fp16 (in place) ----------------
__global__ void rope_h(__half* __restrict__ x, const int* __restrict__ pos_ids,
                       int nheads, float s_mul) {
    int idx = blockIdx.x * blockDim.x + threadIdx.x;
    int total = S_LEN * nheads * 32;
    if (idx >= total) return;
    int i = idx & 31;
    int h = (idx >> 5) % nheads;
    int s = idx / (32 * nheads);
    float pos = (float)pos_ids[s];
    float inv_freq = powf(10000.f, -(float)(2 * i) / 64.f);
    float ang = pos * inv_freq;
    float c = cosf(ang), sn = sinf(ang);
    __half* base = x + ((size_t)s * nheads + h) * HD;
    float x1 = __half2float(base[i]), x2 = __half2float(base[i + 32]);
    base[i]      = __float2half_rn(s_mul * (x1 * c - x2 * sn));
    base[i + 32] = __float2half_rn(s_mul * (x2 * c + x1 * sn));
}

// ---------------- fp16 flash attention, KV tile 128 ----------------
#define KPADH 72
#define VPADT 136
#define FAH_SMEM ((2 * 128 * KPADH + 2 * 64 * VPADT) * 2)

__global__ __launch_bounds__(128) void flash_h(const __half* __restrict__ Qh,
                                               const __half* __restrict__ Kg,
                                               const __half* __restrict__ Vtg,
                                               const float* __restrict__ mask,
                                               __half* __restrict__ O) {
    extern __shared__ __half hs[];
    __half (*Ks)[128][KPADH] = (__half(*)[128][KPADH])hs;
    __half (*Vs)[64][VPADT] = (__half(*)[64][VPADT])(hs + 2 * 128 * KPADH);

    const int tid = threadIdx.x;
    const int warp = tid >> 5, lane = tid & 31;
    const int g = lane >> 2, tg = lane & 3;
    const int wm = warp * 16;

    const int h = blockIdx.y;
    const int kvh = h >> 2;
    const int qbase = blockIdx.x * 64;

    auto load_tiles = [&](int buf, int t) {
#pragma unroll
        for (int u = 0; u < 8; u++) {
            int slot = tid + u * 128;                // 0..1023
            int kr = slot >> 3, kc = (slot & 7) * 8; // K: 128 rows x 8 chunks
            cp_async16(&Ks[buf][kr][kc], Kg + (size_t)(t + kr) * (NKV * HD) + kvh * HD + kc);
            int vr = slot >> 4, vc = (slot & 15) * 8; // V: 64 rows x 16 chunks
            cp_async16(&Vs[buf][vr][vc], Vtg + (size_t)(kvh * HD + vr) * S_LEN + t + vc);
        }
    };

    // Q fragments (pre-scaled 1/8)
    unsigned qa[4][4];
    {
        const __half* Qp = Qh + (size_t)qbase * HID + h * HD;
        const int r0 = wm + g, r1 = wm + g + 8;
#pragma unroll
        for (int ks = 0; ks < 4; ks++) {
            qa[ks][0] = *(const unsigned*)(Qp + (size_t)r0 * HID + ks * 16 + 2 * tg);
            qa[ks][1] = *(const unsigned*)(Qp + (size_t)r1 * HID + ks * 16 + 2 * tg);
            qa[ks][2] = *(const unsigned*)(Qp + (size_t)r0 * HID + ks * 16 + 2 * tg + 8);
            qa[ks][3] = *(const unsigned*)(Qp + (size_t)r1 * HID + ks * 16 + 2 * tg + 8);
        }
    }

    float co[8][4] = {};
    float m_g = -1e30f, m_g8 = -1e30f, l_g = 0.f, l_g8 = 0.f;

    load_tiles(0, 0);
    cp_commit();

    for (int ti = 0; ti < S_LEN / 128; ti++) {
        const int t = ti * 128;
        if (ti + 1 < S_LEN / 128) load_tiles((ti + 1) & 1, t + 128);
        cp_commit();
        cp_wait<1>();
        __syncthreads();

        const int buf = ti & 1;

        // S = Q K^T over 128 keys (16 n-tiles)
        float cs[16][4] = {};
#pragma unroll
        for (int ks = 0; ks < 4; ks++) {
#pragma unroll
            for (int nt = 0; nt < 16; nt++) {
                unsigned b[2];
                b[0] = *(const unsigned*)&Ks[buf][nt * 8 + g][ks * 16 + 2 * tg];
                b[1] = *(const unsigned*)&Ks[buf][nt * 8 + g][ks * 16 + 2 * tg + 8];
                mma_f16(cs[nt], qa[ks], b);
            }
        }

        float mloc_g = -1e30f, mloc_g8 = -1e30f;
#pragma unroll
        for (int nt = 0; nt < 16; nt++) {
            float mk0 = __ldg(mask + t + nt * 8 + 2 * tg);
            float mk1 = __ldg(mask + t + nt * 8 + 2 * tg + 1);
            cs[nt][0] += mk0; cs[nt][1] += mk1;
            cs[nt][2] += mk0; cs[nt][3] += mk1;
            mloc_g  = fmaxf(mloc_g,  fmaxf(cs[nt][0], cs[nt][1]));
            mloc_g8 = fmaxf(mloc_g8, fmaxf(cs[nt][2], cs[nt][3]));
        }
        mloc_g  = fmaxf(mloc_g,  __shfl_xor_sync(0xffffffff, mloc_g, 1));
        mloc_g  = fmaxf(mloc_g,  __shfl_xor_sync(0xffffffff, mloc_g, 2));
        mloc_g8 = fmaxf(mloc_g8, __shfl_xor_sync(0xffffffff, mloc_g8, 1));
        mloc_g8 = fmaxf(mloc_g8, __shfl_xor_sync(0xffffffff, mloc_g8, 2));

        float mn_g  = fmaxf(m_g,  mloc_g);
        float mn_g8 = fmaxf(m_g8, mloc_g8);
        float corr_g  = __expf(m_g - mn_g);
        float corr_g8 = __expf(m_g8 - mn_g8);

        float sum_g = 0.f, sum_g8 = 0.f;
#pragma unroll
        for (int nt = 0; nt < 16; nt++) {
            cs[nt][0] = __expf(cs[nt][0] - mn_g);
            cs[nt][1] = __expf(cs[nt][1] - mn_g);
            cs[nt][2] = __expf(cs[nt][2] - mn_g8);
            cs[nt][3] = __expf(cs[nt][3] - mn_g8);
            sum_g  += cs[nt][0] + cs[nt][1];
            sum_g8 += cs[nt][2] + cs[nt][3];
        }
#pragma unroll
        for (int nt = 0; nt < 8; nt++) {
            co[nt][0] *= corr_g;  co[nt][1] *= corr_g;
            co[nt][2] *= corr_g8; co[nt][3] *= corr_g8;
        }
        sum_g  += __shfl_xor_sync(0xffffffff, sum_g, 1);
        sum_g  += __shfl_xor_sync(0xffffffff, sum_g, 2);
        sum_g8 += __shfl_xor_sync(0xffffffff, sum_g8, 1);
        sum_g8 += __shfl_xor_sync(0xffffffff, sum_g8, 2);
        l_g  = l_g * corr_g + sum_g;
        l_g8 = l_g8 * corr_g8 + sum_g8;
        m_g = mn_g; m_g8 = mn_g8;

        // O += P V  (P from C-fragments, 8 k-chunks of 16 keys)
#pragma unroll
        for (int kk = 0; kk < 8; kk++) {
            unsigned a[4];
            a[0] = pack_half2(cs[2 * kk][0],     cs[2 * kk][1]);
            a[1] = pack_half2(cs[2 * kk][2],     cs[2 * kk][3]);
            a[2] = pack_half2(cs[2 * kk + 1][0], cs[2 * kk + 1][1]);
            a[3] = pack_half2(cs[2 * kk + 1][2], cs[2 * kk + 1][3]);
#pragma unroll
            for (int nt = 0; nt < 8; nt++) {
                unsigned b[2];
                b[0] = *(const unsigned*)&Vs[buf][nt * 8 + g][kk * 16 + 2 * tg];
                b[1] = *(const unsigned*)&Vs[buf][nt * 8 + g][kk * 16 + 2 * tg + 8];
                mma_f16(co[nt], a, b);
            }
        }
        __syncthreads();
    }

    const float inv_g  = 1.f / l_g;
    const float inv_g8 = 1.f / l_g8;
    const int row0 = qbase + wm + g;
#pragma unroll
    for (int nt = 0; nt < 8; nt++) {
        int col = h * HD + nt * 8 + 2 * tg;
        *(unsigned*)(O + (size_t)row0 * HID + col) =
            pack_half2(co[nt][0] * inv_g, co[nt][1] * inv_g);
        *(unsigned*)(O + (size_t)(row0 + 8) * HID + col) =
            pack_half2(co[nt][2] * inv_g8, co[nt][3] * inv_g8);
    }
}

// ---------------- host launcher ----------------
extern "C" void kernel_launch(void* const* d_in, const int* in_sizes, int n_in,
                              void* d_out, int out_size) {
    const float* x    = (const float*)d_in[0];
    const float* mask = (const float*)d_in[1];
    const int*   pos  = (const int*)d_in[2];
    const float* wq   = (const float*)d_in[3];
    const float* wk   = (const float*)d_in[4];
    const float* wv   = (const float*)d_in[5];
    const float* wo   = (const float*)d_in[6];
    float* out = (float*)d_out;

    float *pscale, *ppart;
    __half *pxh, *pwqkv, *pwo, *pqh, *pkh, *pvth, *patth;
    cudaGetSymbolAddress((void**)&pscale, g_scale);
    cudaGetSymbolAddress((void**)&ppart,  g_part);
    cudaGetSymbolAddress((void**)&pxh,    g_xh);
    cudaGetSymbolAddress((void**)&pwqkv,  g_wqkv);
    cudaGetSymbolAddress((void**)&pwo,    g_wo);
    cudaGetSymbolAddress((void**)&pqh,    g_qh);
    cudaGetSymbolAddress((void**)&pkh,    g_kh);
    cudaGetSymbolAddress((void**)&pvth,   g_vth);
    cudaGetSymbolAddress((void**)&patth,  g_atth);

    cudaFuncSetAttribute(hgemm_qkv, cudaFuncAttributeMaxDynamicSharedMemorySize, HGEMM_SMEM);
    cudaFuncSetAttribute(hgemm_out, cudaFuncAttributeMaxDynamicSharedMemorySize, HGEMM_SMEM);
    cudaFuncSetAttribute(flash_h, cudaFuncAttributeMaxDynamicSharedMemorySize, FAH_SMEM);

    // scales
    absmean_all_partial<<<dim3(256, 4), 256>>>(wq, wk, wv, wo, ppart);
    absmean_all_final<<<4, 256>>>(ppart, pscale);

    // pre-passes
    quantize_all_h<<<dim3(256, 4), 256>>>(wq, wk, wv, wo, pwqkv, pwo, pscale);
    cvt_x_half<<<(S_LEN * HID / 4 + 1023) / 1024, 256>>>(x, pxh, S_LEN * HID / 4);

    // fused QKV projection
    hgemm_qkv<<<dim3(24, 16), 256, HGEMM_SMEM>>>(pxh, pwqkv, pqh, pkh, pvth, pscale);

    // RoPE (Q pre-scaled by 1/sqrt(64))
    rope_h<<<(S_LEN * NH * 32 + 255) / 256, 256>>>(pqh, pos, NH, 0.125f);
    rope_h<<<(S_LEN * NKV * 32 + 255) / 256, 256>>>(pkh, pos, NKV, 1.0f);

    // flash attention (KV tile 128)
    flash_h<<<dim3(S_LEN / 64, NH), 128, FAH_SMEM>>>(pqh, pkh, pvth, mask, patth);

    // output projection
    hgemm_out<<<dim3(16, 16), 256, HGEMM_SMEM>>>(patth, pwo, out, pscale + 3);
}